// round 6
// baseline (speedup 1.0000x reference)
#include <cuda_runtime.h>
#include <cuda_bf16.h>
#include <cstdint>
#include <math.h>

#define NDIM 768
#define NTOK 512
#define BSZ 2
#define MALL 1024
#define NHEADS 12
#define DHEAD 64
#define DMLP 3072
#define NDEPTH 4
#define QKVW 2304
#define PATCHES 512
#define NBH (BSZ*NHEADS)

__device__ __forceinline__ uint32_t smem_u32(const void* p){
    uint32_t a;
    asm("{ .reg .u64 t; cvta.to.shared.u64 t, %1; cvt.u32.u64 %0, t; }" : "=r"(a) : "l"(p));
    return a;
}
#define CPA16(d, s) asm volatile("cp.async.cg.shared.global [%0], [%1], 16;" :: "r"(d), "l"(s))
#define CP_COMMIT() asm volatile("cp.async.commit_group;" ::: "memory")
#define CP_WAIT1()  asm volatile("cp.async.wait_group 1;" ::: "memory")
#define CP_WAIT0()  asm volatile("cp.async.wait_group 0;" ::: "memory")

__device__ __forceinline__ void ldm4(uint32_t addr, uint32_t* r){
    asm volatile("ldmatrix.sync.aligned.m8n8.x4.shared.b16 {%0,%1,%2,%3}, [%4];"
        : "=r"(r[0]), "=r"(r[1]), "=r"(r[2]), "=r"(r[3]) : "r"(addr));
}
__device__ __forceinline__ void mma16816(float* c, const uint32_t* a, const uint32_t* b){
    asm volatile("mma.sync.aligned.m16n8k16.row.col.f32.bf16.bf16.f32 "
        "{%0,%1,%2,%3}, {%4,%5,%6,%7}, {%8,%9}, {%0,%1,%2,%3};"
        : "+f"(c[0]), "+f"(c[1]), "+f"(c[2]), "+f"(c[3])
        : "r"(a[0]), "r"(a[1]), "r"(a[2]), "r"(a[3]), "r"(b[0]), "r"(b[1]));
}
__device__ __forceinline__ void split2(float v, __nv_bfloat16& h, __nv_bfloat16& l){
    h = __float2bfloat16(v);
    l = __float2bfloat16(v - __bfloat162float(h));
}
__device__ __forceinline__ uint32_t pack_hi(float x, float y){
    __nv_bfloat162 t = __float22bfloat162_rn(make_float2(x, y));
    return *reinterpret_cast<uint32_t*>(&t);
}
__device__ __forceinline__ uint32_t pack_lo(float x, float y){
    float hx = __bfloat162float(__float2bfloat16(x));
    float hy = __bfloat162float(__float2bfloat16(y));
    __nv_bfloat162 t = __float22bfloat162_rn(make_float2(x - hx, y - hy));
    return *reinterpret_cast<uint32_t*>(&t);
}

// ---------------- scratch ----------------
__device__ __align__(256) __nv_bfloat16 g_pat_h[MALL*PATCHES], g_pat_l[MALL*PATCHES];
__device__ __align__(256) __nv_bfloat16 g_cw_h[NDIM*PATCHES], g_cw_l[NDIM*PATCHES];
__device__ __align__(256) __nv_bfloat16 g_wqkvT_h[NDEPTH*QKVW*NDIM], g_wqkvT_l[NDEPTH*QKVW*NDIM];
__device__ __align__(256) __nv_bfloat16 g_woT_h[NDEPTH*NDIM*NDIM], g_woT_l[NDEPTH*NDIM*NDIM];
__device__ __align__(256) __nv_bfloat16 g_w1T_h[NDEPTH*DMLP*NDIM], g_w1T_l[NDEPTH*DMLP*NDIM];
__device__ __align__(256) __nv_bfloat16 g_w2T_h[NDEPTH*NDIM*DMLP], g_w2T_l[NDEPTH*NDIM*DMLP];
__device__ __align__(256) float         g_x[MALL*NDIM];
__device__ __align__(256) __nv_bfloat16 g_h_h[MALL*NDIM], g_h_l[MALL*NDIM];
__device__ __align__(256) __nv_bfloat16 g_qkv_h[MALL*QKVW], g_qkv_l[MALL*QKVW];
__device__ __align__(256) __nv_bfloat16 g_vt_h[NBH*DHEAD*NTOK], g_vt_l[NBH*DHEAD*NTOK];
__device__ __align__(256) __nv_bfloat16 g_o_h[MALL*NDIM], g_o_l[MALL*NDIM];
__device__ __align__(256) __nv_bfloat16 g_m_h[MALL*DMLP], g_m_l[MALL*DMLP];

// ---------------- prep kernels ----------------
__global__ void im2col_split(const float* __restrict__ vol,
                             __nv_bfloat16* __restrict__ oh, __nv_bfloat16* __restrict__ ol){
    int idx = blockIdx.x * 256 + threadIdx.x;
    int m = idx & 511, tkn = idx >> 9, n = tkn & 511, b = tkn >> 9;
    int k = m & 7, j = (m >> 3) & 7, i = m >> 6;
    int pw = n & 7, ph = (n >> 3) & 7, pd = n >> 6;
    float v = vol[((long)b << 18) + (pd*8+i)*4096 + (ph*8+j)*64 + (pw*8+k)];
    __nv_bfloat16 h, l; split2(v, h, l);
    oh[idx] = h; ol[idx] = l;
}
__global__ void split_plain(const float* __restrict__ in,
                            __nv_bfloat16* __restrict__ oh, __nv_bfloat16* __restrict__ ol, int n){
    int idx = blockIdx.x * 256 + threadIdx.x;
    if (idx >= n) return;
    __nv_bfloat16 h, l; split2(in[idx], h, l);
    oh[idx] = h; ol[idx] = l;
}
__global__ void wt_split(const float* __restrict__ in,
                         __nv_bfloat16* __restrict__ oh, __nv_bfloat16* __restrict__ ol, int R, int C){
    __shared__ float tf[32][33];
    int z = blockIdx.z;
    const float* ip = in + (long)z * R * C;
    int r0 = blockIdx.y * 32, c0 = blockIdx.x * 32;
    int tx = threadIdx.x, ty = threadIdx.y;
#pragma unroll
    for (int i = 0; i < 4; i++)
        tf[ty + 8*i][tx] = ip[(long)(r0 + ty + 8*i) * C + c0 + tx];
    __syncthreads();
    long ob = (long)z * R * C;
#pragma unroll
    for (int i = 0; i < 4; i++) {
        __nv_bfloat16 h, l; split2(tf[tx][ty + 8*i], h, l);
        long oi = ob + (long)(c0 + ty + 8*i) * R + r0 + tx;
        oh[oi] = h; ol[oi] = l;
    }
}
__global__ void vt_split(const __nv_bfloat16* __restrict__ qh, const __nv_bfloat16* __restrict__ ql,
                         __nv_bfloat16* __restrict__ vh, __nv_bfloat16* __restrict__ vl){
    __shared__ __nv_bfloat16 th[32][33], tl[32][33];
    int z = blockIdx.z, b = z / NHEADS, h = z % NHEADS;
    int t0 = blockIdx.x * 32, d0 = blockIdx.y * 32;
    int tx = threadIdx.x, ty = threadIdx.y;
    const long base = (long)b * NTOK * QKVW + 2 * NDIM + h * DHEAD;
#pragma unroll
    for (int i = 0; i < 4; i++) {
        long gi = base + (long)(t0 + ty + 8*i) * QKVW + d0 + tx;
        th[ty + 8*i][tx] = qh[gi]; tl[ty + 8*i][tx] = ql[gi];
    }
    __syncthreads();
    long ob = (long)z * DHEAD * NTOK;
#pragma unroll
    for (int i = 0; i < 4; i++) {
        long oi = ob + (long)(d0 + ty + 8*i) * NTOK + t0 + tx;
        vh[oi] = th[tx][ty + 8*i]; vl[oi] = tl[tx][ty + 8*i];
    }
}

// ---------------- LN: single-pass (sum + sumsq) ----------------
template <int SPLIT>
__global__ void ln_kernel(const float* __restrict__ x, const float* __restrict__ w,
                          const float* __restrict__ bb, float* __restrict__ of,
                          __nv_bfloat16* __restrict__ oh, __nv_bfloat16* __restrict__ ol){
    __shared__ float red1[8], red2[8];
    const int row = blockIdx.x, t = threadIdx.x;
    const float* xp = x + (long)row * NDIM;
    float v0 = xp[t], v1 = xp[t+256], v2 = xp[t+512];
    float s1 = v0 + v1 + v2;
    float s2 = v0*v0 + v1*v1 + v2*v2;
#pragma unroll
    for (int o = 16; o; o >>= 1) {
        s1 += __shfl_xor_sync(~0u, s1, o);
        s2 += __shfl_xor_sync(~0u, s2, o);
    }
    if ((t & 31) == 0) { red1[t >> 5] = s1; red2[t >> 5] = s2; }
    __syncthreads();
    if (t < 32) {
        float r1 = (t < 8) ? red1[t] : 0.0f;
        float r2 = (t < 8) ? red2[t] : 0.0f;
#pragma unroll
        for (int o = 4; o; o >>= 1) {
            r1 += __shfl_xor_sync(~0u, r1, o);
            r2 += __shfl_xor_sync(~0u, r2, o);
        }
        if (t == 0) { red1[0] = r1; red2[0] = r2; }
    }
    __syncthreads();
    float mean = red1[0] * (1.0f / NDIM);
    float var  = red2[0] * (1.0f / NDIM) - mean * mean;
    float rs = rsqrtf(var + 1e-5f);
    float y0 = (v0-mean)*rs*w[t]     + bb[t];
    float y1 = (v1-mean)*rs*w[t+256] + bb[t+256];
    float y2 = (v2-mean)*rs*w[t+512] + bb[t+512];
    long o0 = (long)row * NDIM;
    if (SPLIT) {
        __nv_bfloat16 h, l;
        split2(y0,h,l); oh[o0+t]=h;     ol[o0+t]=l;
        split2(y1,h,l); oh[o0+t+256]=h; ol[o0+t+256]=l;
        split2(y2,h,l); oh[o0+t+512]=h; ol[o0+t+512]=l;
    } else {
        of[o0+t]=y0; of[o0+t+256]=y1; of[o0+t+512]=y2;
    }
}

// ---------------- fused flash attention ----------------
// grid (8 qtiles, 24 bh), 256 thr = 2M x 4N warps.
// Q tile 64 rows; kv chunks of 128 tokens; online softmax; per-warp k-slice PV;
// final 4-way O reduction through smem.
#define FA_QOFF   0
#define FA_KOFF   18432
#define FA_VOFF   92160
#define FA_SCR    161792
#define FA_SMEM   164352
#define FA_KBUF   36864
#define FA_VBUF   34816

__global__ void __launch_bounds__(256, 1) flash_attn(
    const __nv_bfloat16* __restrict__ qkv_h, const __nv_bfloat16* __restrict__ qkv_l,
    const __nv_bfloat16* __restrict__ vt_h,  const __nv_bfloat16* __restrict__ vt_l,
    __nv_bfloat16* __restrict__ o_h, __nv_bfloat16* __restrict__ o_l)
{
    extern __shared__ __align__(128) char smem_raw[];
    uint32_t sb = smem_u32(smem_raw);
    const uint32_t sQ = sb + FA_QOFF;
    float* redm  = reinterpret_cast<float*>(smem_raw + FA_SCR);          // [64][4]
    float* redl  = redm + 256;                                           // [64][4]
    float* m_run = redl + 256;                                           // [64]
    float* l_run = m_run + 64;                                           // [64]
    float* osum  = reinterpret_cast<float*>(smem_raw + FA_KOFF);         // [4][64][68]

    const int tid = threadIdx.x, lane = tid & 31, warp = tid >> 5;
    const int warpM = warp & 1, warpN = warp >> 1;
    const int qt = blockIdx.x, z = blockIdx.y, b = z / NHEADS, h = z % NHEADS;
    const long qbase = ((long)b*NTOK + qt*64)*QKVW + h*DHEAD;
    const long kbase = (long)b*NTOK*QKVW + NDIM + h*DHEAD;
    const long vbase = (long)z*DHEAD*NTOK;
    const int L = lane & 7, jj = lane >> 3;

    if (tid < 64) { m_run[tid] = -1e30f; l_run[tid] = 0.0f; }

    // load Q (group 0, together with kv chunk 0)
#pragma unroll
    for (int i = 0; i < 2; i++) {
        int idx = tid + i*256, r = idx >> 3, c = idx & 7;
        long g = qbase + (long)r*QKVW + c*8;
        CPA16(sQ + r*144 + c*16, qkv_h + g);
        CPA16(sQ + 9216 + r*144 + c*16, qkv_l + g);
    }
    // kv loader
    auto load_kv = [&](int j){
        uint32_t kb = sb + FA_KOFF + (j & 1) * FA_KBUF;
        uint32_t vb = sb + FA_VOFF + (j & 1) * FA_VBUF;
#pragma unroll
        for (int i = 0; i < 4; i++) {
            int idx = tid + i*256, r = idx >> 3, c = idx & 7;
            long g = kbase + (long)(j*128 + r)*QKVW + c*8;
            CPA16(kb + r*144 + c*16, qkv_h + g);
            CPA16(kb + 18432 + r*144 + c*16, qkv_l + g);
        }
#pragma unroll
        for (int i = 0; i < 4; i++) {
            int idx = tid + i*256, r = idx >> 4, c = idx & 15;
            long g = vbase + (long)r*NTOK + j*128 + c*8;
            CPA16(vb + r*272 + c*16, vt_h + g);
            CPA16(vb + 17408 + r*272 + c*16, vt_l + g);
        }
    };
    load_kv(0); CP_COMMIT();
    load_kv(1); CP_COMMIT();

    float oacc[2][8][4];
#pragma unroll
    for (int a = 0; a < 2; a++)
#pragma unroll
        for (int b2 = 0; b2 < 8; b2++)
#pragma unroll
            for (int c = 0; c < 4; c++) oacc[a][b2][c] = 0.0f;

    for (int j = 0; j < 4; j++) {
        if (j < 3) CP_WAIT1(); else CP_WAIT0();
        __syncthreads();                           // sync A: buffers + m_run ready
        uint32_t kb = sb + FA_KOFF + (j & 1) * FA_KBUF;
        uint32_t vb = sb + FA_VOFF + (j & 1) * FA_VBUF;

        // ---- S = Q K^T ----
        float s[2][4][4];
#pragma unroll
        for (int a = 0; a < 2; a++)
#pragma unroll
            for (int n = 0; n < 4; n++)
#pragma unroll
                for (int c = 0; c < 4; c++) s[a][n][c] = 0.0f;
#pragma unroll
        for (int ks = 0; ks < 4; ks++) {
            uint32_t ah_[2][4], al_[2][4];
#pragma unroll
            for (int mi = 0; mi < 2; mi++) {
                int mrow = warpM*32 + mi*16 + (jj & 1)*8 + L;
                int kcol = ks*16 + (jj >> 1)*8;
                uint32_t ad = sQ + mrow*144 + kcol*2;
                ldm4(ad, ah_[mi]); ldm4(ad + 9216, al_[mi]);
            }
            uint32_t bh_[2][4], bl_[2][4];
#pragma unroll
            for (int np = 0; np < 2; np++) {
                int nrow = warpN*32 + np*16 + (jj >> 1)*8 + L;
                int kcol = ks*16 + (jj & 1)*8;
                uint32_t bd = kb + nrow*144 + kcol*2;
                ldm4(bd, bh_[np]); ldm4(bd + 18432, bl_[np]);
            }
#pragma unroll
            for (int mi = 0; mi < 2; mi++)
#pragma unroll
                for (int np = 0; np < 2; np++)
#pragma unroll
                    for (int si = 0; si < 2; si++) {
                        uint32_t fh[2] = { bh_[np][si*2], bh_[np][si*2+1] };
                        uint32_t fl[2] = { bl_[np][si*2], bl_[np][si*2+1] };
                        float* c = s[mi][np*2 + si];
                        mma16816(c, ah_[mi], fh);
                        mma16816(c, ah_[mi], fl);
                        mma16816(c, al_[mi], fh);
                    }
        }
        // scale
#pragma unroll
        for (int a = 0; a < 2; a++)
#pragma unroll
            for (int n = 0; n < 4; n++)
#pragma unroll
                for (int c = 0; c < 4; c++) s[a][n][c] *= 0.125f;

        // ---- row max ----
#pragma unroll
        for (int mi = 0; mi < 2; mi++)
#pragma unroll
            for (int hf = 0; hf < 2; hf++) {
                float mx = -1e30f;
#pragma unroll
                for (int nt = 0; nt < 4; nt++) {
                    mx = fmaxf(mx, s[mi][nt][hf*2 + 0]);
                    mx = fmaxf(mx, s[mi][nt][hf*2 + 1]);
                }
                mx = fmaxf(mx, __shfl_xor_sync(~0u, mx, 1));
                mx = fmaxf(mx, __shfl_xor_sync(~0u, mx, 2));
                if ((lane & 3) == 0)
                    redm[(warpM*32 + mi*16 + hf*8 + (lane >> 2))*4 + warpN] = mx;
            }
        __syncthreads();                            // sync B

        float mn[2][2], fct[2][2];
#pragma unroll
        for (int mi = 0; mi < 2; mi++)
#pragma unroll
            for (int hf = 0; hf < 2; hf++) {
                int row = warpM*32 + mi*16 + hf*8 + (lane >> 2);
                float mc = fmaxf(fmaxf(redm[row*4+0], redm[row*4+1]),
                                 fmaxf(redm[row*4+2], redm[row*4+3]));
                float mo = m_run[row];
                float m2 = fmaxf(mo, mc);
                mn[mi][hf] = m2;
                fct[mi][hf] = __expf(mo - m2);
            }
        // ---- exp + row sum ----
#pragma unroll
        for (int mi = 0; mi < 2; mi++)
#pragma unroll
            for (int hf = 0; hf < 2; hf++) {
                float sum = 0.0f;
#pragma unroll
                for (int nt = 0; nt < 4; nt++) {
                    float p0 = __expf(s[mi][nt][hf*2+0] - mn[mi][hf]);
                    float p1 = __expf(s[mi][nt][hf*2+1] - mn[mi][hf]);
                    s[mi][nt][hf*2+0] = p0; s[mi][nt][hf*2+1] = p1;
                    sum += p0 + p1;
                }
                sum += __shfl_xor_sync(~0u, sum, 1);
                sum += __shfl_xor_sync(~0u, sum, 2);
                if ((lane & 3) == 0)
                    redl[(warpM*32 + mi*16 + hf*8 + (lane >> 2))*4 + warpN] = sum;
            }
        // ---- rescale O ----
#pragma unroll
        for (int mi = 0; mi < 2; mi++)
#pragma unroll
            for (int nt = 0; nt < 8; nt++) {
                oacc[mi][nt][0] *= fct[mi][0]; oacc[mi][nt][1] *= fct[mi][0];
                oacc[mi][nt][2] *= fct[mi][1]; oacc[mi][nt][3] *= fct[mi][1];
            }
        // ---- O += P V  (warp k-slice = its 32 tokens) ----
#pragma unroll
        for (int ks2 = 0; ks2 < 2; ks2++) {
            uint32_t pa_h[2][4], pa_l[2][4];
#pragma unroll
            for (int mi = 0; mi < 2; mi++) {
                float* s0 = s[mi][2*ks2];
                float* s1 = s[mi][2*ks2 + 1];
                pa_h[mi][0] = pack_hi(s0[0], s0[1]); pa_h[mi][1] = pack_hi(s0[2], s0[3]);
                pa_h[mi][2] = pack_hi(s1[0], s1[1]); pa_h[mi][3] = pack_hi(s1[2], s1[3]);
                pa_l[mi][0] = pack_lo(s0[0], s0[1]); pa_l[mi][1] = pack_lo(s0[2], s0[3]);
                pa_l[mi][2] = pack_lo(s1[0], s1[1]); pa_l[mi][3] = pack_lo(s1[2], s1[3]);
            }
            uint32_t vh_[4][4], vl_[4][4];
#pragma unroll
            for (int np = 0; np < 4; np++) {
                int nrow = np*16 + (jj >> 1)*8 + L;
                int kcol = warpN*32 + ks2*16 + (jj & 1)*8;
                uint32_t bd = vb + nrow*272 + kcol*2;
                ldm4(bd, vh_[np]); ldm4(bd + 17408, vl_[np]);
            }
#pragma unroll
            for (int mi = 0; mi < 2; mi++)
#pragma unroll
                for (int np = 0; np < 4; np++)
#pragma unroll
                    for (int si = 0; si < 2; si++) {
                        uint32_t fh[2] = { vh_[np][si*2], vh_[np][si*2+1] };
                        uint32_t fl[2] = { vl_[np][si*2], vl_[np][si*2+1] };
                        float* c = oacc[mi][np*2 + si];
                        mma16816(c, pa_h[mi], fh);
                        mma16816(c, pa_h[mi], fl);
                        mma16816(c, pa_l[mi], fh);
                    }
        }
        __syncthreads();                            // sync C
        if (warpN == 0 && (lane & 3) == 0) {
#pragma unroll
            for (int mi = 0; mi < 2; mi++)
#pragma unroll
                for (int hf = 0; hf < 2; hf++) {
                    int row = warpM*32 + mi*16 + hf*8 + (lane >> 2);
                    float ls = redl[row*4+0] + redl[row*4+1] + redl[row*4+2] + redl[row*4+3];
                    m_run[row] = mn[mi][hf];
                    l_run[row] = l_run[row]*fct[mi][hf] + ls;
                }
        }
        if (j + 2 < 4) { load_kv(j + 2); CP_COMMIT(); }
    }
    __syncthreads();   // l_run final + all smem reads done (osum aliases K/V area)

    // ---- per-warp partial O -> smem, 4-way reduce, normalize, split, store ----
#pragma unroll
    for (int mi = 0; mi < 2; mi++)
#pragma unroll
        for (int nt = 0; nt < 8; nt++) {
            int col = nt*8 + (lane & 3)*2;
#pragma unroll
            for (int hf = 0; hf < 2; hf++) {
                int row = warpM*32 + mi*16 + hf*8 + (lane >> 2);
                osum[(warpN*64 + row)*68 + col]     = oacc[mi][nt][hf*2+0];
                osum[(warpN*64 + row)*68 + col + 1] = oacc[mi][nt][hf*2+1];
            }
        }
    __syncthreads();
    {
        int r = tid >> 2, c0 = (tid & 3) * 16;
        float inv = 1.0f / l_run[r];
        long obase = ((long)(b*NTOK + qt*64 + r))*NDIM + h*DHEAD + c0;
#pragma unroll
        for (int i = 0; i < 16; i += 2) {
            float va = (osum[(0*64+r)*68 + c0+i] + osum[(1*64+r)*68 + c0+i] +
                        osum[(2*64+r)*68 + c0+i] + osum[(3*64+r)*68 + c0+i]) * inv;
            float vb2 = (osum[(0*64+r)*68 + c0+i+1] + osum[(1*64+r)*68 + c0+i+1] +
                         osum[(2*64+r)*68 + c0+i+1] + osum[(3*64+r)*68 + c0+i+1]) * inv;
            __nv_bfloat16 h0, l0, h1, l1;
            split2(va, h0, l0); split2(vb2, h1, l1);
            __nv_bfloat162 hp; hp.x = h0; hp.y = h1;
            __nv_bfloat162 lp; lp.x = l0; lp.y = l1;
            *reinterpret_cast<__nv_bfloat162*>(o_h + obase + i) = hp;
            *reinterpret_cast<__nv_bfloat162*>(o_l + obase + i) = lp;
        }
    }
}

// ---------------- split-bf16 GEMM via mma.sync (unchanged from R5) ----------------
template <int BM, int BN>
__device__ __forceinline__ void ld_stage(uint32_t sb, int tid,
    const __nv_bfloat16* pAh, const __nv_bfloat16* pAl,
    const __nv_bfloat16* pBh, const __nv_bfloat16* pBl,
    long long lda, long long ldb, int row0, int col0, int k0){
    constexpr int ASZ = BM*80, BSZ2 = BN*80;
#pragma unroll
    for (int i = 0; i < BM/64; i++) {
        int ch = tid + i*256;
        int r = ch >> 2, c = ch & 3;
        uint32_t so = r*80 + c*16;
        long long go = (long long)(row0 + r) * lda + k0 + c*8;
        CPA16(sb + so, pAh + go);
        CPA16(sb + ASZ + so, pAl + go);
    }
#pragma unroll
    for (int i = 0; i < BN/64; i++) {
        int ch = tid + i*256;
        int r = ch >> 2, c = ch & 3;
        uint32_t so = r*80 + c*16;
        long long go = (long long)(col0 + r) * ldb + k0 + c*8;
        CPA16(sb + 2*ASZ + so, pBh + go);
        CPA16(sb + 2*ASZ + BSZ2 + so, pBl + go);
    }
}

template <int BM, int BN, int EPI>
__global__ void __launch_bounds__(256, 1) mma_gemm(
    const __nv_bfloat16* __restrict__ Ah, const __nv_bfloat16* __restrict__ Al,
    long long lda,
    const __nv_bfloat16* __restrict__ Bh, const __nv_bfloat16* __restrict__ Bl,
    long long ldb,
    float* __restrict__ Cf, __nv_bfloat16* __restrict__ Oh, __nv_bfloat16* __restrict__ Ol,
    long long ldc,
    const float* __restrict__ bias, const float* __restrict__ pos,
    int K)
{
    extern __shared__ __align__(128) char smem_raw[];
    uint32_t sb = smem_u32(smem_raw);
    constexpr int ASZ = BM*80, BSZ2 = BN*80;
    constexpr int BUF = 2*ASZ + 2*BSZ2;
    constexpr int MW = BM/32;
    constexpr int NW = 8/MW;
    constexpr int WN = BN/NW;
    constexpr int NP = WN/16;
    constexpr int NT = WN/8;

    const int tid = threadIdx.x, lane = tid & 31, warp = tid >> 5;
    const int warpM = warp % MW, warpN = warp / MW;
    const int row0 = blockIdx.y * BM, col0 = blockIdx.x * BN;

    float acc[2][NT][4];
#pragma unroll
    for (int a = 0; a < 2; a++)
#pragma unroll
        for (int b = 0; b < NT; b++)
#pragma unroll
            for (int c = 0; c < 4; c++) acc[a][b][c] = 0.0f;

    const int nst = K >> 5;
    ld_stage<BM,BN>(sb, tid, Ah, Al, Bh, Bl, lda, ldb, row0, col0, 0);
    CP_COMMIT();
    if (nst > 1) {
        ld_stage<BM,BN>(sb + BUF, tid, Ah, Al, Bh, Bl, lda, ldb, row0, col0, 32);
        CP_COMMIT();
    }

    const int L = lane & 7, jj = lane >> 3;
    for (int st = 0; st < nst; st++) {
        if (st < nst - 1) CP_WAIT1(); else CP_WAIT0();
        __syncthreads();
        if (st + 2 < nst) {
            ld_stage<BM,BN>(sb + ((st+2)%3)*BUF, tid, Ah, Al, Bh, Bl,
                            lda, ldb, row0, col0, (st+2)*32);
            CP_COMMIT();
        }
        uint32_t base = sb + (st % 3) * BUF;
#pragma unroll
        for (int ks = 0; ks < 2; ks++) {
            uint32_t ah_[2][4], al_[2][4];
#pragma unroll
            for (int mi = 0; mi < 2; mi++) {
                int mrow = warpM*32 + mi*16 + (jj & 1)*8 + L;
                int kcol = ks*16 + (jj >> 1)*8;
                uint32_t ad = base + mrow*80 + kcol*2;
                ldm4(ad, ah_[mi]);
                ldm4(ad + ASZ, al_[mi]);
            }
            uint32_t bh_[NP][4], bl_[NP][4];
#pragma unroll
            for (int np = 0; np < NP; np++) {
                int nrow = warpN*WN + np*16 + (jj >> 1)*8 + L;
                int kcol = ks*16 + (jj & 1)*8;
                uint32_t bd = base + 2*ASZ + nrow*80 + kcol*2;
                ldm4(bd, bh_[np]);
                ldm4(bd + BSZ2, bl_[np]);
            }
#pragma unroll
            for (int mi = 0; mi < 2; mi++)
#pragma unroll
                for (int np = 0; np < NP; np++)
#pragma unroll
                    for (int si = 0; si < 2; si++) {
                        uint32_t fh[2] = { bh_[np][si*2], bh_[np][si*2+1] };
                        uint32_t fl[2] = { bl_[np][si*2], bl_[np][si*2+1] };
                        float* c = acc[mi][np*2 + si];
                        mma16816(c, ah_[mi], fh);
                        mma16816(c, ah_[mi], fl);
                        mma16816(c, al_[mi], fh);
                    }
        }
    }

#pragma unroll
    for (int mi = 0; mi < 2; mi++)
#pragma unroll
        for (int nt = 0; nt < NT; nt++) {
            float* c = acc[mi][nt];
            int col = col0 + warpN*WN + nt*8 + (lane & 3)*2;
#pragma unroll
            for (int hf = 0; hf < 2; hf++) {
                int row = row0 + warpM*32 + mi*16 + (lane >> 2) + hf*8;
                float v0 = c[hf*2 + 0], v1 = c[hf*2 + 1];
                if (EPI == 1) {
                    float2* cp = reinterpret_cast<float2*>(Cf + (long long)row*ldc + col);
                    float2 old = *cp;
                    *cp = make_float2(old.x + v0 + bias[col], old.y + v1 + bias[col+1]);
                } else if (EPI == 3) {
                    const float2* pp = reinterpret_cast<const float2*>(
                        pos + (long long)(row & (NTOK-1))*ldc + col);
                    float2 pv = *pp;
                    float2* cp = reinterpret_cast<float2*>(Cf + (long long)row*ldc + col);
                    *cp = make_float2(v0 + bias[col] + pv.x, v1 + bias[col+1] + pv.y);
                } else {
                    if (EPI == 2) {
                        v0 = tanhf(v0 + bias[col]);
                        v1 = tanhf(v1 + bias[col+1]);
                    }
                    __nv_bfloat16 h0, l0, h1, l1;
                    split2(v0, h0, l0); split2(v1, h1, l1);
                    long long off = (long long)row*ldc + col;
                    __nv_bfloat162 hp; hp.x = h0; hp.y = h1;
                    *reinterpret_cast<__nv_bfloat162*>(Oh + off) = hp;
                    __nv_bfloat162 lp; lp.x = l0; lp.y = l1;
                    *reinterpret_cast<__nv_bfloat162*>(Ol + off) = lp;
                }
            }
        }
}

// ---------------- host ----------------
extern "C" void kernel_launch(void* const* d_in, const int* in_sizes, int n_in,
                              void* d_out, int out_size)
{
    const float* volume    = (const float*)d_in[0];
    const float* conv_w    = (const float*)d_in[1];
    const float* conv_b    = (const float*)d_in[2];
    const float* pos_embed = (const float*)d_in[3];
    const float* ln1_w     = (const float*)d_in[4];
    const float* ln1_b     = (const float*)d_in[5];
    const float* w_qkv     = (const float*)d_in[6];
    const float* w_o       = (const float*)d_in[7];
    const float* b_o       = (const float*)d_in[8];
    const float* ln2_w     = (const float*)d_in[9];
    const float* ln2_b     = (const float*)d_in[10];
    const float* w1        = (const float*)d_in[11];
    const float* b1        = (const float*)d_in[12];
    const float* w2        = (const float*)d_in[13];
    const float* b2        = (const float*)d_in[14];
    const float* lnf_w     = (const float*)d_in[15];
    const float* lnf_b     = (const float*)d_in[16];
    float* out = (float*)d_out;

    __nv_bfloat16 *pat_h,*pat_l,*cw_h,*cw_l,*wqT_h,*wqT_l,*woT_h,*woT_l;
    __nv_bfloat16 *w1T_h,*w1T_l,*w2T_h,*w2T_l,*h_h,*h_l,*qkv_h,*qkv_l;
    __nv_bfloat16 *vt_h,*vt_l,*o_h,*o_l,*m_h,*m_l;
    float *x;
    cudaGetSymbolAddress((void**)&pat_h, g_pat_h); cudaGetSymbolAddress((void**)&pat_l, g_pat_l);
    cudaGetSymbolAddress((void**)&cw_h, g_cw_h);   cudaGetSymbolAddress((void**)&cw_l, g_cw_l);
    cudaGetSymbolAddress((void**)&wqT_h, g_wqkvT_h); cudaGetSymbolAddress((void**)&wqT_l, g_wqkvT_l);
    cudaGetSymbolAddress((void**)&woT_h, g_woT_h); cudaGetSymbolAddress((void**)&woT_l, g_woT_l);
    cudaGetSymbolAddress((void**)&w1T_h, g_w1T_h); cudaGetSymbolAddress((void**)&w1T_l, g_w1T_l);
    cudaGetSymbolAddress((void**)&w2T_h, g_w2T_h); cudaGetSymbolAddress((void**)&w2T_l, g_w2T_l);
    cudaGetSymbolAddress((void**)&x, g_x);
    cudaGetSymbolAddress((void**)&h_h, g_h_h);     cudaGetSymbolAddress((void**)&h_l, g_h_l);
    cudaGetSymbolAddress((void**)&qkv_h, g_qkv_h); cudaGetSymbolAddress((void**)&qkv_l, g_qkv_l);
    cudaGetSymbolAddress((void**)&vt_h, g_vt_h);   cudaGetSymbolAddress((void**)&vt_l, g_vt_l);
    cudaGetSymbolAddress((void**)&o_h, g_o_h);     cudaGetSymbolAddress((void**)&o_l, g_o_l);
    cudaGetSymbolAddress((void**)&m_h, g_m_h);     cudaGetSymbolAddress((void**)&m_l, g_m_l);

    const int S_128_128 = 3*(2*128*80 + 2*128*80);
    const int S_128_192 = 3*(2*128*80 + 2*192*80);
    const int S_64_64   = 3*(2*64*80  + 2*64*80);
    cudaFuncSetAttribute(mma_gemm<128,128,4>, cudaFuncAttributeMaxDynamicSharedMemorySize, S_128_128);
    cudaFuncSetAttribute(mma_gemm<128,192,2>, cudaFuncAttributeMaxDynamicSharedMemorySize, S_128_192);
    cudaFuncSetAttribute(mma_gemm<64,64,1>,   cudaFuncAttributeMaxDynamicSharedMemorySize, S_64_64);
    cudaFuncSetAttribute(mma_gemm<64,64,3>,   cudaFuncAttributeMaxDynamicSharedMemorySize, S_64_64);
    cudaFuncSetAttribute(flash_attn, cudaFuncAttributeMaxDynamicSharedMemorySize, FA_SMEM);

    dim3 tb(32, 8);

    im2col_split<<<(MALL*PATCHES)/256, 256>>>(volume, pat_h, pat_l);
    split_plain<<<(NDIM*PATCHES)/256, 256>>>(conv_w, cw_h, cw_l, NDIM*PATCHES);
    wt_split<<<dim3(QKVW/32, NDIM/32, NDEPTH), tb>>>(w_qkv, wqT_h, wqT_l, NDIM, QKVW);
    wt_split<<<dim3(NDIM/32, NDIM/32, NDEPTH), tb>>>(w_o, woT_h, woT_l, NDIM, NDIM);
    wt_split<<<dim3(DMLP/32, NDIM/32, NDEPTH), tb>>>(w1, w1T_h, w1T_l, NDIM, DMLP);
    wt_split<<<dim3(NDIM/32, DMLP/32, NDEPTH), tb>>>(w2, w2T_h, w2T_l, DMLP, NDIM);

    mma_gemm<64,64,3><<<dim3(NDIM/64, MALL/64), 256, S_64_64>>>(
        pat_h, pat_l, PATCHES, cw_h, cw_l, PATCHES,
        x, nullptr, nullptr, NDIM, conv_b, pos_embed, PATCHES);

    for (int l = 0; l < NDEPTH; ++l) {
        ln_kernel<1><<<MALL, 256>>>(x, ln1_w + l*NDIM, ln1_b + l*NDIM, nullptr, h_h, h_l);
        mma_gemm<128,128,4><<<dim3(QKVW/128, MALL/128), 256, S_128_128>>>(
            h_h, h_l, NDIM, wqT_h + (long)l*QKVW*NDIM, wqT_l + (long)l*QKVW*NDIM, NDIM,
            nullptr, qkv_h, qkv_l, QKVW, nullptr, nullptr, NDIM);
        vt_split<<<dim3(NTOK/32, DHEAD/32, NBH), tb>>>(qkv_h, qkv_l, vt_h, vt_l);
        flash_attn<<<dim3(NTOK/64, NBH), 256, FA_SMEM>>>(qkv_h, qkv_l, vt_h, vt_l, o_h, o_l);
        mma_gemm<64,64,1><<<dim3(NDIM/64, MALL/64), 256, S_64_64>>>(
            o_h, o_l, NDIM, woT_h + (long)l*NDIM*NDIM, woT_l + (long)l*NDIM*NDIM, NDIM,
            x, nullptr, nullptr, NDIM, b_o + l*NDIM, nullptr, NDIM);
        ln_kernel<1><<<MALL, 256>>>(x, ln2_w + l*NDIM, ln2_b + l*NDIM, nullptr, h_h, h_l);
        mma_gemm<128,192,2><<<dim3(DMLP/192, MALL/128), 256, S_128_192>>>(
            h_h, h_l, NDIM, w1T_h + (long)l*DMLP*NDIM, w1T_l + (long)l*DMLP*NDIM, NDIM,
            nullptr, m_h, m_l, DMLP, b1 + l*DMLP, nullptr, NDIM);
        mma_gemm<64,64,1><<<dim3(NDIM/64, MALL/64), 256, S_64_64>>>(
            m_h, m_l, DMLP, w2T_h + (long)l*NDIM*DMLP, w2T_l + (long)l*NDIM*DMLP, DMLP,
            x, nullptr, nullptr, NDIM, b2 + l*NDIM, nullptr, DMLP);
    }

    ln_kernel<0><<<MALL, 256>>>(x, lnf_w, lnf_b, out, nullptr, nullptr);
}

// round 7
// speedup vs baseline: 1.4826x; 1.4826x over previous
#include <cuda_runtime.h>
#include <cuda_bf16.h>
#include <cstdint>
#include <math.h>

#define NDIM 768
#define NTOK 512
#define BSZ 2
#define MALL 1024
#define NHEADS 12
#define DHEAD 64
#define DMLP 3072
#define NDEPTH 4
#define QKVW 2304
#define PATCHES 512
#define NBH (BSZ*NHEADS)

__device__ __forceinline__ uint32_t smem_u32(const void* p){
    uint32_t a;
    asm("{ .reg .u64 t; cvta.to.shared.u64 t, %1; cvt.u32.u64 %0, t; }" : "=r"(a) : "l"(p));
    return a;
}
#define CPA16(d, s) asm volatile("cp.async.cg.shared.global [%0], [%1], 16;" :: "r"(d), "l"(s))
#define CP_COMMIT() asm volatile("cp.async.commit_group;" ::: "memory")
#define CP_WAIT1()  asm volatile("cp.async.wait_group 1;" ::: "memory")
#define CP_WAIT0()  asm volatile("cp.async.wait_group 0;" ::: "memory")

__device__ __forceinline__ void ldm4(uint32_t addr, uint32_t* r){
    asm volatile("ldmatrix.sync.aligned.m8n8.x4.shared.b16 {%0,%1,%2,%3}, [%4];"
        : "=r"(r[0]), "=r"(r[1]), "=r"(r[2]), "=r"(r[3]) : "r"(addr));
}
__device__ __forceinline__ void mma16816(float* c, const uint32_t* a, const uint32_t* b){
    asm volatile("mma.sync.aligned.m16n8k16.row.col.f32.bf16.bf16.f32 "
        "{%0,%1,%2,%3}, {%4,%5,%6,%7}, {%8,%9}, {%0,%1,%2,%3};"
        : "+f"(c[0]), "+f"(c[1]), "+f"(c[2]), "+f"(c[3])
        : "r"(a[0]), "r"(a[1]), "r"(a[2]), "r"(a[3]), "r"(b[0]), "r"(b[1]));
}
__device__ __forceinline__ void split2(float v, __nv_bfloat16& h, __nv_bfloat16& l){
    h = __float2bfloat16(v);
    l = __float2bfloat16(v - __bfloat162float(h));
}

// ---------------- scratch ----------------
__device__ __align__(256) __nv_bfloat16 g_pat_h[MALL*PATCHES], g_pat_l[MALL*PATCHES];
__device__ __align__(256) __nv_bfloat16 g_cw_h[NDIM*PATCHES], g_cw_l[NDIM*PATCHES];
__device__ __align__(256) __nv_bfloat16 g_wqkvT_h[NDEPTH*QKVW*NDIM], g_wqkvT_l[NDEPTH*QKVW*NDIM];
__device__ __align__(256) __nv_bfloat16 g_woT_h[NDEPTH*NDIM*NDIM], g_woT_l[NDEPTH*NDIM*NDIM];
__device__ __align__(256) __nv_bfloat16 g_w1T_h[NDEPTH*DMLP*NDIM], g_w1T_l[NDEPTH*DMLP*NDIM];
__device__ __align__(256) __nv_bfloat16 g_w2T_h[NDEPTH*NDIM*DMLP], g_w2T_l[NDEPTH*NDIM*DMLP];
__device__ __align__(256) float         g_x[MALL*NDIM];
__device__ __align__(256) __nv_bfloat16 g_h_h[MALL*NDIM], g_h_l[MALL*NDIM];
__device__ __align__(256) __nv_bfloat16 g_qkv_h[MALL*QKVW], g_qkv_l[MALL*QKVW];
__device__ __align__(256) float         g_scores[NBH*NTOK*NTOK];
__device__ __align__(256) __nv_bfloat16 g_p_h[NBH*NTOK*NTOK], g_p_l[NBH*NTOK*NTOK];
__device__ __align__(256) __nv_bfloat16 g_vt_h[NBH*DHEAD*NTOK], g_vt_l[NBH*DHEAD*NTOK];
__device__ __align__(256) __nv_bfloat16 g_o_h[MALL*NDIM], g_o_l[MALL*NDIM];
__device__ __align__(256) __nv_bfloat16 g_m_h[MALL*DMLP], g_m_l[MALL*DMLP];

// ---------------- prep kernels ----------------
__global__ void im2col_split(const float* __restrict__ vol,
                             __nv_bfloat16* __restrict__ oh, __nv_bfloat16* __restrict__ ol){
    int idx = blockIdx.x * 256 + threadIdx.x;
    int m = idx & 511, tkn = idx >> 9, n = tkn & 511, b = tkn >> 9;
    int k = m & 7, j = (m >> 3) & 7, i = m >> 6;
    int pw = n & 7, ph = (n >> 3) & 7, pd = n >> 6;
    float v = vol[((long)b << 18) + (pd*8+i)*4096 + (ph*8+j)*64 + (pw*8+k)];
    __nv_bfloat16 h, l; split2(v, h, l);
    oh[idx] = h; ol[idx] = l;
}
__global__ void split_plain(const float* __restrict__ in,
                            __nv_bfloat16* __restrict__ oh, __nv_bfloat16* __restrict__ ol, int n){
    int idx = blockIdx.x * 256 + threadIdx.x;
    if (idx >= n) return;
    __nv_bfloat16 h, l; split2(in[idx], h, l);
    oh[idx] = h; ol[idx] = l;
}
__global__ void wt_split(const float* __restrict__ in,
                         __nv_bfloat16* __restrict__ oh, __nv_bfloat16* __restrict__ ol, int R, int C){
    __shared__ float tf[32][33];
    int z = blockIdx.z;
    const float* ip = in + (long)z * R * C;
    int r0 = blockIdx.y * 32, c0 = blockIdx.x * 32;
    int tx = threadIdx.x, ty = threadIdx.y;
#pragma unroll
    for (int i = 0; i < 4; i++)
        tf[ty + 8*i][tx] = ip[(long)(r0 + ty + 8*i) * C + c0 + tx];
    __syncthreads();
    long ob = (long)z * R * C;
#pragma unroll
    for (int i = 0; i < 4; i++) {
        __nv_bfloat16 h, l; split2(tf[tx][ty + 8*i], h, l);
        long oi = ob + (long)(c0 + ty + 8*i) * R + r0 + tx;
        oh[oi] = h; ol[oi] = l;
    }
}
__global__ void vt_split(const __nv_bfloat16* __restrict__ qh, const __nv_bfloat16* __restrict__ ql,
                         __nv_bfloat16* __restrict__ vh, __nv_bfloat16* __restrict__ vl){
    __shared__ __nv_bfloat16 th[32][33], tl[32][33];
    int z = blockIdx.z, b = z / NHEADS, h = z % NHEADS;
    int t0 = blockIdx.x * 32, d0 = blockIdx.y * 32;
    int tx = threadIdx.x, ty = threadIdx.y;
    const long base = (long)b * NTOK * QKVW + 2 * NDIM + h * DHEAD;
#pragma unroll
    for (int i = 0; i < 4; i++) {
        long gi = base + (long)(t0 + ty + 8*i) * QKVW + d0 + tx;
        th[ty + 8*i][tx] = qh[gi]; tl[ty + 8*i][tx] = ql[gi];
    }
    __syncthreads();
    long ob = (long)z * DHEAD * NTOK;
#pragma unroll
    for (int i = 0; i < 4; i++) {
        long oi = ob + (long)(d0 + ty + 8*i) * NTOK + t0 + tx;
        vh[oi] = th[tx][ty + 8*i]; vl[oi] = tl[tx][ty + 8*i];
    }
}

// ---------------- LN: single-pass (sum + sumsq) ----------------
template <int SPLIT>
__global__ void ln_kernel(const float* __restrict__ x, const float* __restrict__ w,
                          const float* __restrict__ bb, float* __restrict__ of,
                          __nv_bfloat16* __restrict__ oh, __nv_bfloat16* __restrict__ ol){
    __shared__ float red1[8], red2[8];
    const int row = blockIdx.x, t = threadIdx.x;
    const float* xp = x + (long)row * NDIM;
    float v0 = xp[t], v1 = xp[t+256], v2 = xp[t+512];
    float s1 = v0 + v1 + v2;
    float s2 = v0*v0 + v1*v1 + v2*v2;
#pragma unroll
    for (int o = 16; o; o >>= 1) {
        s1 += __shfl_xor_sync(~0u, s1, o);
        s2 += __shfl_xor_sync(~0u, s2, o);
    }
    if ((t & 31) == 0) { red1[t >> 5] = s1; red2[t >> 5] = s2; }
    __syncthreads();
    if (t < 32) {
        float r1 = (t < 8) ? red1[t] : 0.0f;
        float r2 = (t < 8) ? red2[t] : 0.0f;
#pragma unroll
        for (int o = 4; o; o >>= 1) {
            r1 += __shfl_xor_sync(~0u, r1, o);
            r2 += __shfl_xor_sync(~0u, r2, o);
        }
        if (t == 0) { red1[0] = r1; red2[0] = r2; }
    }
    __syncthreads();
    float mean = red1[0] * (1.0f / NDIM);
    float var  = red2[0] * (1.0f / NDIM) - mean * mean;
    float rs = rsqrtf(var + 1e-5f);
    float y0 = (v0-mean)*rs*w[t]     + bb[t];
    float y1 = (v1-mean)*rs*w[t+256] + bb[t+256];
    float y2 = (v2-mean)*rs*w[t+512] + bb[t+512];
    long o0 = (long)row * NDIM;
    if (SPLIT) {
        __nv_bfloat16 h, l;
        split2(y0,h,l); oh[o0+t]=h;     ol[o0+t]=l;
        split2(y1,h,l); oh[o0+t+256]=h; ol[o0+t+256]=l;
        split2(y2,h,l); oh[o0+t+512]=h; ol[o0+t+512]=l;
    } else {
        of[o0+t]=y0; of[o0+t+256]=y1; of[o0+t+512]=y2;
    }
}

// ---------------- softmax ----------------
__global__ void softmax_split(const float* __restrict__ sc,
                              __nv_bfloat16* __restrict__ ph, __nv_bfloat16* __restrict__ pl){
    __shared__ float redm[4], reds[4];
    long rb = (long)blockIdx.x * NTOK;
    const int t = threadIdx.x;
    float4 v = *reinterpret_cast<const float4*>(&sc[rb + t*4]);
    float m = fmaxf(fmaxf(v.x, v.y), fmaxf(v.z, v.w));
#pragma unroll
    for (int o = 16; o; o >>= 1) m = fmaxf(m, __shfl_xor_sync(~0u, m, o));
    if ((t & 31) == 0) redm[t >> 5] = m;
    __syncthreads();
    m = fmaxf(fmaxf(redm[0], redm[1]), fmaxf(redm[2], redm[3]));
    v.x = __expf(v.x-m); v.y = __expf(v.y-m); v.z = __expf(v.z-m); v.w = __expf(v.w-m);
    float s = v.x + v.y + v.z + v.w;
#pragma unroll
    for (int o = 16; o; o >>= 1) s += __shfl_xor_sync(~0u, s, o);
    if ((t & 31) == 0) reds[t >> 5] = s;
    __syncthreads();
    s = reds[0] + reds[1] + reds[2] + reds[3];
    float inv = 1.0f / s;
    __nv_bfloat16 h0,l0,h1,l1,h2,l2,h3,l3;
    split2(v.x*inv,h0,l0); split2(v.y*inv,h1,l1); split2(v.z*inv,h2,l2); split2(v.w*inv,h3,l3);
    long off = rb + t*4;
    __nv_bfloat162 a, b;
    a.x=h0; a.y=h1; b.x=h2; b.y=h3;
    reinterpret_cast<__nv_bfloat162*>(ph+off)[0]=a; reinterpret_cast<__nv_bfloat162*>(ph+off)[1]=b;
    a.x=l0; a.y=l1; b.x=l2; b.y=l3;
    reinterpret_cast<__nv_bfloat162*>(pl+off)[0]=a; reinterpret_cast<__nv_bfloat162*>(pl+off)[1]=b;
}

// ---------------- split-bf16 GEMM via mma.sync ----------------
template <int BM, int BN>
__device__ __forceinline__ void ld_stage(uint32_t sb, int tid,
    const __nv_bfloat16* pAh, const __nv_bfloat16* pAl,
    const __nv_bfloat16* pBh, const __nv_bfloat16* pBl,
    long long lda, long long ldb, int row0, int col0, int k0){
    constexpr int ASZ = BM*80, BSZ2 = BN*80;
#pragma unroll
    for (int i = 0; i < BM/64; i++) {
        int ch = tid + i*256;
        int r = ch >> 2, c = ch & 3;
        uint32_t so = r*80 + c*16;
        long long go = (long long)(row0 + r) * lda + k0 + c*8;
        CPA16(sb + so, pAh + go);
        CPA16(sb + ASZ + so, pAl + go);
    }
#pragma unroll
    for (int i = 0; i < BN/64; i++) {
        int ch = tid + i*256;
        int r = ch >> 2, c = ch & 3;
        uint32_t so = r*80 + c*16;
        long long go = (long long)(col0 + r) * ldb + k0 + c*8;
        CPA16(sb + 2*ASZ + so, pBh + go);
        CPA16(sb + 2*ASZ + BSZ2 + so, pBl + go);
    }
}

template <int BM, int BN, int EPI, int OCC>
__global__ void __launch_bounds__(256, OCC) mma_gemm(
    const __nv_bfloat16* __restrict__ Ah, const __nv_bfloat16* __restrict__ Al,
    long long lda, long long aSB, long long aSH,
    const __nv_bfloat16* __restrict__ Bh, const __nv_bfloat16* __restrict__ Bl,
    long long ldb, long long bSB, long long bSH,
    float* __restrict__ Cf, __nv_bfloat16* __restrict__ Oh, __nv_bfloat16* __restrict__ Ol,
    long long ldc, long long cSB, long long cSH,
    const float* __restrict__ bias, const float* __restrict__ pos,
    float scale, int K, int heads)
{
    extern __shared__ __align__(128) char smem_raw[];
    uint32_t sb = smem_u32(smem_raw);
    constexpr int ASZ = BM*80, BSZ2 = BN*80;
    constexpr int BUF = 2*ASZ + 2*BSZ2;
    constexpr int MW = BM/32;
    constexpr int NW = 8/MW;
    constexpr int WN = BN/NW;
    constexpr int NP = WN/16;
    constexpr int NT = WN/8;

    const int tid = threadIdx.x, lane = tid & 31, warp = tid >> 5;
    const int warpM = warp % MW, warpN = warp / MW;
    const int z = blockIdx.z, zb = z / heads, zh = z % heads;
    const __nv_bfloat16* pAh = Ah + zb*aSB + zh*aSH;
    const __nv_bfloat16* pAl = Al + zb*aSB + zh*aSH;
    const __nv_bfloat16* pBh = Bh + zb*bSB + zh*bSH;
    const __nv_bfloat16* pBl = Bl + zb*bSB + zh*bSH;
    const long long cOff = zb*cSB + zh*cSH;
    const int row0 = blockIdx.y * BM, col0 = blockIdx.x * BN;

    float acc[2][NT][4];
#pragma unroll
    for (int a = 0; a < 2; a++)
#pragma unroll
        for (int b = 0; b < NT; b++)
#pragma unroll
            for (int c = 0; c < 4; c++) acc[a][b][c] = 0.0f;

    const int nst = K >> 5;
    ld_stage<BM,BN>(sb, tid, pAh, pAl, pBh, pBl, lda, ldb, row0, col0, 0);
    CP_COMMIT();
    if (nst > 1) {
        ld_stage<BM,BN>(sb + BUF, tid, pAh, pAl, pBh, pBl, lda, ldb, row0, col0, 32);
        CP_COMMIT();
    }

    const int L = lane & 7, jj = lane >> 3;
    for (int st = 0; st < nst; st++) {
        if (st < nst - 1) CP_WAIT1(); else CP_WAIT0();
        __syncthreads();
        if (st + 2 < nst) {
            ld_stage<BM,BN>(sb + ((st+2)%3)*BUF, tid, pAh, pAl, pBh, pBl,
                            lda, ldb, row0, col0, (st+2)*32);
            CP_COMMIT();
        }
        uint32_t base = sb + (st % 3) * BUF;
#pragma unroll
        for (int ks = 0; ks < 2; ks++) {
            uint32_t ah_[2][4], al_[2][4];
#pragma unroll
            for (int mi = 0; mi < 2; mi++) {
                int mrow = warpM*32 + mi*16 + (jj & 1)*8 + L;
                int kcol = ks*16 + (jj >> 1)*8;
                uint32_t ad = base + mrow*80 + kcol*2;
                ldm4(ad, ah_[mi]);
                ldm4(ad + ASZ, al_[mi]);
            }
            uint32_t bh_[NP][4], bl_[NP][4];
#pragma unroll
            for (int np = 0; np < NP; np++) {
                int nrow = warpN*WN + np*16 + (jj >> 1)*8 + L;
                int kcol = ks*16 + (jj & 1)*8;
                uint32_t bd = base + 2*ASZ + nrow*80 + kcol*2;
                ldm4(bd, bh_[np]);
                ldm4(bd + BSZ2, bl_[np]);
            }
#pragma unroll
            for (int mi = 0; mi < 2; mi++)
#pragma unroll
                for (int np = 0; np < NP; np++)
#pragma unroll
                    for (int si = 0; si < 2; si++) {
                        uint32_t fh[2] = { bh_[np][si*2], bh_[np][si*2+1] };
                        uint32_t fl[2] = { bl_[np][si*2], bl_[np][si*2+1] };
                        float* c = acc[mi][np*2 + si];
                        mma16816(c, ah_[mi], fh);
                        mma16816(c, ah_[mi], fl);
                        mma16816(c, al_[mi], fh);
                    }
        }
    }

#pragma unroll
    for (int mi = 0; mi < 2; mi++)
#pragma unroll
        for (int nt = 0; nt < NT; nt++) {
            float* c = acc[mi][nt];
            int col = col0 + warpN*WN + nt*8 + (lane & 3)*2;
#pragma unroll
            for (int hf = 0; hf < 2; hf++) {
                int row = row0 + warpM*32 + mi*16 + (lane >> 2) + hf*8;
                float v0 = c[hf*2 + 0], v1 = c[hf*2 + 1];
                if (EPI == 0) {
                    float2* cp = reinterpret_cast<float2*>(Cf + cOff + (long long)row*ldc + col);
                    *cp = make_float2(v0*scale, v1*scale);
                } else if (EPI == 1) {
                    float2* cp = reinterpret_cast<float2*>(Cf + cOff + (long long)row*ldc + col);
                    float2 old = *cp;
                    *cp = make_float2(old.x + v0 + bias[col], old.y + v1 + bias[col+1]);
                } else if (EPI == 3) {
                    const float2* pp = reinterpret_cast<const float2*>(
                        pos + (long long)(row & (NTOK-1))*ldc + col);
                    float2 pv = *pp;
                    float2* cp = reinterpret_cast<float2*>(Cf + (long long)row*ldc + col);
                    *cp = make_float2(v0 + bias[col] + pv.x, v1 + bias[col+1] + pv.y);
                } else {
                    if (EPI == 2) {
                        v0 = tanhf(v0 + bias[col]);
                        v1 = tanhf(v1 + bias[col+1]);
                    }
                    __nv_bfloat16 h0, l0, h1, l1;
                    split2(v0, h0, l0); split2(v1, h1, l1);
                    long long off = cOff + (long long)row*ldc + col;
                    __nv_bfloat162 hp; hp.x = h0; hp.y = h1;
                    *reinterpret_cast<__nv_bfloat162*>(Oh + off) = hp;
                    __nv_bfloat162 lp; lp.x = l0; lp.y = l1;
                    *reinterpret_cast<__nv_bfloat162*>(Ol + off) = lp;
                }
            }
        }
}

// ---------------- host ----------------
extern "C" void kernel_launch(void* const* d_in, const int* in_sizes, int n_in,
                              void* d_out, int out_size)
{
    const float* volume    = (const float*)d_in[0];
    const float* conv_w    = (const float*)d_in[1];
    const float* conv_b    = (const float*)d_in[2];
    const float* pos_embed = (const float*)d_in[3];
    const float* ln1_w     = (const float*)d_in[4];
    const float* ln1_b     = (const float*)d_in[5];
    const float* w_qkv     = (const float*)d_in[6];
    const float* w_o       = (const float*)d_in[7];
    const float* b_o       = (const float*)d_in[8];
    const float* ln2_w     = (const float*)d_in[9];
    const float* ln2_b     = (const float*)d_in[10];
    const float* w1        = (const float*)d_in[11];
    const float* b1        = (const float*)d_in[12];
    const float* w2        = (const float*)d_in[13];
    const float* b2        = (const float*)d_in[14];
    const float* lnf_w     = (const float*)d_in[15];
    const float* lnf_b     = (const float*)d_in[16];
    float* out = (float*)d_out;

    __nv_bfloat16 *pat_h,*pat_l,*cw_h,*cw_l,*wqT_h,*wqT_l,*woT_h,*woT_l;
    __nv_bfloat16 *w1T_h,*w1T_l,*w2T_h,*w2T_l,*h_h,*h_l,*qkv_h,*qkv_l;
    __nv_bfloat16 *p_h,*p_l,*vt_h,*vt_l,*o_h,*o_l,*m_h,*m_l;
    float *x, *scores;
    cudaGetSymbolAddress((void**)&pat_h, g_pat_h); cudaGetSymbolAddress((void**)&pat_l, g_pat_l);
    cudaGetSymbolAddress((void**)&cw_h, g_cw_h);   cudaGetSymbolAddress((void**)&cw_l, g_cw_l);
    cudaGetSymbolAddress((void**)&wqT_h, g_wqkvT_h); cudaGetSymbolAddress((void**)&wqT_l, g_wqkvT_l);
    cudaGetSymbolAddress((void**)&woT_h, g_woT_h); cudaGetSymbolAddress((void**)&woT_l, g_woT_l);
    cudaGetSymbolAddress((void**)&w1T_h, g_w1T_h); cudaGetSymbolAddress((void**)&w1T_l, g_w1T_l);
    cudaGetSymbolAddress((void**)&w2T_h, g_w2T_h); cudaGetSymbolAddress((void**)&w2T_l, g_w2T_l);
    cudaGetSymbolAddress((void**)&x, g_x);
    cudaGetSymbolAddress((void**)&h_h, g_h_h);     cudaGetSymbolAddress((void**)&h_l, g_h_l);
    cudaGetSymbolAddress((void**)&qkv_h, g_qkv_h); cudaGetSymbolAddress((void**)&qkv_l, g_qkv_l);
    cudaGetSymbolAddress((void**)&scores, g_scores);
    cudaGetSymbolAddress((void**)&p_h, g_p_h);     cudaGetSymbolAddress((void**)&p_l, g_p_l);
    cudaGetSymbolAddress((void**)&vt_h, g_vt_h);   cudaGetSymbolAddress((void**)&vt_l, g_vt_l);
    cudaGetSymbolAddress((void**)&o_h, g_o_h);     cudaGetSymbolAddress((void**)&o_l, g_o_l);
    cudaGetSymbolAddress((void**)&m_h, g_m_h);     cudaGetSymbolAddress((void**)&m_l, g_m_l);

    const int S_128_128 = 3*(2*128*80 + 2*128*80);
    const int S_128_192 = 3*(2*128*80 + 2*192*80);
    const int S_64_64   = 3*(2*64*80  + 2*64*80);
    cudaFuncSetAttribute((const void*)mma_gemm<128,128,0,1>, cudaFuncAttributeMaxDynamicSharedMemorySize, S_128_128);
    cudaFuncSetAttribute((const void*)mma_gemm<128,128,4,1>, cudaFuncAttributeMaxDynamicSharedMemorySize, S_128_128);
    cudaFuncSetAttribute((const void*)mma_gemm<128,192,2,1>, cudaFuncAttributeMaxDynamicSharedMemorySize, S_128_192);
    cudaFuncSetAttribute((const void*)mma_gemm<64,64,1,2>,   cudaFuncAttributeMaxDynamicSharedMemorySize, S_64_64);
    cudaFuncSetAttribute((const void*)mma_gemm<64,64,3,2>,   cudaFuncAttributeMaxDynamicSharedMemorySize, S_64_64);
    cudaFuncSetAttribute((const void*)mma_gemm<64,64,4,2>,   cudaFuncAttributeMaxDynamicSharedMemorySize, S_64_64);

    dim3 tb(32, 8);

    im2col_split<<<(MALL*PATCHES)/256, 256>>>(volume, pat_h, pat_l);
    split_plain<<<(NDIM*PATCHES)/256, 256>>>(conv_w, cw_h, cw_l, NDIM*PATCHES);
    wt_split<<<dim3(QKVW/32, NDIM/32, NDEPTH), tb>>>(w_qkv, wqT_h, wqT_l, NDIM, QKVW);
    wt_split<<<dim3(NDIM/32, NDIM/32, NDEPTH), tb>>>(w_o, woT_h, woT_l, NDIM, NDIM);
    wt_split<<<dim3(DMLP/32, NDIM/32, NDEPTH), tb>>>(w1, w1T_h, w1T_l, NDIM, DMLP);
    wt_split<<<dim3(NDIM/32, DMLP/32, NDEPTH), tb>>>(w2, w2T_h, w2T_l, DMLP, NDIM);

    // patch embed: x = patches @ conv_w^T + conv_b + pos  (192 CTAs, occ 2)
    mma_gemm<64,64,3,2><<<dim3(NDIM/64, MALL/64, 1), 256, S_64_64>>>(
        pat_h, pat_l, PATCHES, 0, 0, cw_h, cw_l, PATCHES, 0, 0,
        x, nullptr, nullptr, NDIM, 0, 0, conv_b, pos_embed, 1.f, PATCHES, 1);

    for (int l = 0; l < NDEPTH; ++l) {
        ln_kernel<1><<<MALL, 256>>>(x, ln1_w + l*NDIM, ln1_b + l*NDIM, nullptr, h_h, h_l);
        mma_gemm<128,128,4,1><<<dim3(QKVW/128, MALL/128, 1), 256, S_128_128>>>(
            h_h, h_l, NDIM, 0, 0, wqT_h + (long)l*QKVW*NDIM, wqT_l + (long)l*QKVW*NDIM, NDIM, 0, 0,
            nullptr, qkv_h, qkv_l, QKVW, 0, 0, nullptr, nullptr, 1.f, NDIM, 1);
        mma_gemm<128,128,0,1><<<dim3(NTOK/128, NTOK/128, NBH), 256, S_128_128>>>(
            qkv_h, qkv_l, QKVW, (long long)NTOK*QKVW, DHEAD,
            qkv_h + NDIM, qkv_l + NDIM, QKVW, (long long)NTOK*QKVW, DHEAD,
            scores, nullptr, nullptr, NTOK, (long long)NHEADS*NTOK*NTOK, (long long)NTOK*NTOK,
            nullptr, nullptr, 0.125f, DHEAD, NHEADS);
        softmax_split<<<NBH*NTOK, 128>>>(scores, p_h, p_l);
        vt_split<<<dim3(NTOK/32, DHEAD/32, NBH), tb>>>(qkv_h, qkv_l, vt_h, vt_l);
        mma_gemm<64,64,4,2><<<dim3(1, NTOK/64, NBH), 256, S_64_64>>>(
            p_h, p_l, NTOK, (long long)NHEADS*NTOK*NTOK, (long long)NTOK*NTOK,
            vt_h, vt_l, NTOK, (long long)NHEADS*DHEAD*NTOK, (long long)DHEAD*NTOK,
            nullptr, o_h, o_l, NDIM, (long long)NTOK*NDIM, DHEAD,
            nullptr, nullptr, 1.f, NTOK, NHEADS);
        mma_gemm<64,64,1,2><<<dim3(NDIM/64, MALL/64, 1), 256, S_64_64>>>(
            o_h, o_l, NDIM, 0, 0, woT_h + (long)l*NDIM*NDIM, woT_l + (long)l*NDIM*NDIM, NDIM, 0, 0,
            x, nullptr, nullptr, NDIM, 0, 0, b_o + l*NDIM, nullptr, 1.f, NDIM, 1);
        ln_kernel<1><<<MALL, 256>>>(x, ln2_w + l*NDIM, ln2_b + l*NDIM, nullptr, h_h, h_l);
        mma_gemm<128,192,2,1><<<dim3(DMLP/192, MALL/128, 1), 256, S_128_192>>>(
            h_h, h_l, NDIM, 0, 0, w1T_h + (long)l*DMLP*NDIM, w1T_l + (long)l*DMLP*NDIM, NDIM, 0, 0,
            nullptr, m_h, m_l, DMLP, 0, 0, b1 + l*DMLP, nullptr, 1.f, NDIM, 1);
        mma_gemm<64,64,1,2><<<dim3(NDIM/64, MALL/64, 1), 256, S_64_64>>>(
            m_h, m_l, DMLP, 0, 0, w2T_h + (long)l*NDIM*DMLP, w2T_l + (long)l*NDIM*DMLP, DMLP, 0, 0,
            x, nullptr, nullptr, NDIM, 0, 0, b2 + l*NDIM, nullptr, 1.f, DMLP, 1);
    }

    ln_kernel<0><<<MALL, 256>>>(x, lnf_w, lnf_b, out, nullptr, nullptr);
}

// round 8
// speedup vs baseline: 1.8491x; 1.2472x over previous
#include <cuda_runtime.h>
#include <cuda_fp16.h>
#include <cstdint>
#include <math.h>

#define NDIM 768
#define NTOK 512
#define BSZ 2
#define MALL 1024
#define NHEADS 12
#define DHEAD 64
#define DMLP 3072
#define NDEPTH 4
#define QKVW 2304
#define PATCHES 512
#define NBH (BSZ*NHEADS)

__device__ __forceinline__ uint32_t smem_u32(const void* p){
    uint32_t a;
    asm("{ .reg .u64 t; cvta.to.shared.u64 t, %1; cvt.u32.u64 %0, t; }" : "=r"(a) : "l"(p));
    return a;
}
#define CPA16(d, s) asm volatile("cp.async.cg.shared.global [%0], [%1], 16;" :: "r"(d), "l"(s))
#define CP_COMMIT() asm volatile("cp.async.commit_group;" ::: "memory")
#define CP_WAIT1()  asm volatile("cp.async.wait_group 1;" ::: "memory")
#define CP_WAIT0()  asm volatile("cp.async.wait_group 0;" ::: "memory")

__device__ __forceinline__ void ldm4(uint32_t addr, uint32_t* r){
    asm volatile("ldmatrix.sync.aligned.m8n8.x4.shared.b16 {%0,%1,%2,%3}, [%4];"
        : "=r"(r[0]), "=r"(r[1]), "=r"(r[2]), "=r"(r[3]) : "r"(addr));
}
__device__ __forceinline__ void mma16816(float* c, const uint32_t* a, const uint32_t* b){
    asm volatile("mma.sync.aligned.m16n8k16.row.col.f32.f16.f16.f32 "
        "{%0,%1,%2,%3}, {%4,%5,%6,%7}, {%8,%9}, {%0,%1,%2,%3};"
        : "+f"(c[0]), "+f"(c[1]), "+f"(c[2]), "+f"(c[3])
        : "r"(a[0]), "r"(a[1]), "r"(a[2]), "r"(a[3]), "r"(b[0]), "r"(b[1]));
}
__device__ __forceinline__ void split2h(float v, __half& h, __half& l){
    h = __float2half_rn(v);
    l = __float2half_rn(v - __half2float(h));
}

// ---------------- scratch ----------------
__device__ __align__(256) __half g_pat_h[MALL*PATCHES], g_pat_l[MALL*PATCHES];
__device__ __align__(256) __half g_cw[NDIM*PATCHES];
__device__ __align__(256) __half g_wqkvT[NDEPTH*QKVW*NDIM];
__device__ __align__(256) __half g_woT[NDEPTH*NDIM*NDIM];
__device__ __align__(256) __half g_w1T[NDEPTH*DMLP*NDIM];
__device__ __align__(256) __half g_w2T[NDEPTH*NDIM*DMLP];
__device__ __align__(256) float  g_x[MALL*NDIM];
__device__ __align__(256) __half g_h_h[MALL*NDIM], g_h_l[MALL*NDIM];
__device__ __align__(256) __half g_qkv_h[MALL*QKVW], g_qkv_l[MALL*QKVW];
__device__ __align__(256) float  g_scores[NBH*NTOK*NTOK];
__device__ __align__(256) __half g_p_h[NBH*NTOK*NTOK], g_p_l[NBH*NTOK*NTOK];
__device__ __align__(256) __half g_vt_h[NBH*DHEAD*NTOK], g_vt_l[NBH*DHEAD*NTOK];
__device__ __align__(256) __half g_o_h[MALL*NDIM], g_o_l[MALL*NDIM];
__device__ __align__(256) __half g_m_h[MALL*DMLP], g_m_l[MALL*DMLP];

// ---------------- prep kernels ----------------
__global__ void im2col_split(const float* __restrict__ vol,
                             __half* __restrict__ oh, __half* __restrict__ ol){
    int idx = blockIdx.x * 256 + threadIdx.x;
    int m = idx & 511, tkn = idx >> 9, n = tkn & 511, b = tkn >> 9;
    int k = m & 7, j = (m >> 3) & 7, i = m >> 6;
    int pw = n & 7, ph = (n >> 3) & 7, pd = n >> 6;
    float v = vol[((long)b << 18) + (pd*8+i)*4096 + (ph*8+j)*64 + (pw*8+k)];
    __half h, l; split2h(v, h, l);
    oh[idx] = h; ol[idx] = l;
}
__global__ void conv_half(const float* __restrict__ in, __half* __restrict__ o, int n){
    int idx = blockIdx.x * 256 + threadIdx.x;
    if (idx >= n) return;
    o[idx] = __float2half_rn(in[idx]);
}
// transpose+convert: in fp32 [L][R][C] -> out fp16 [L][C][R]
__global__ void wt_half(const float* __restrict__ in, __half* __restrict__ o, int R, int C){
    __shared__ float tf[32][33];
    int z = blockIdx.z;
    const float* ip = in + (long)z * R * C;
    int r0 = blockIdx.y * 32, c0 = blockIdx.x * 32;
    int tx = threadIdx.x, ty = threadIdx.y;
#pragma unroll
    for (int i = 0; i < 4; i++)
        tf[ty + 8*i][tx] = ip[(long)(r0 + ty + 8*i) * C + c0 + tx];
    __syncthreads();
    long ob = (long)z * R * C;
#pragma unroll
    for (int i = 0; i < 4; i++)
        o[ob + (long)(c0 + ty + 8*i) * R + r0 + tx] = __float2half_rn(tf[tx][ty + 8*i]);
}
__global__ void vt_split(const __half* __restrict__ qh, const __half* __restrict__ ql,
                         __half* __restrict__ vh, __half* __restrict__ vl){
    __shared__ __half th[32][33], tl[32][33];
    int z = blockIdx.z, b = z / NHEADS, h = z % NHEADS;
    int t0 = blockIdx.x * 32, d0 = blockIdx.y * 32;
    int tx = threadIdx.x, ty = threadIdx.y;
    const long base = (long)b * NTOK * QKVW + 2 * NDIM + h * DHEAD;
#pragma unroll
    for (int i = 0; i < 4; i++) {
        long gi = base + (long)(t0 + ty + 8*i) * QKVW + d0 + tx;
        th[ty + 8*i][tx] = qh[gi]; tl[ty + 8*i][tx] = ql[gi];
    }
    __syncthreads();
    long ob = (long)z * DHEAD * NTOK;
#pragma unroll
    for (int i = 0; i < 4; i++) {
        long oi = ob + (long)(d0 + ty + 8*i) * NTOK + t0 + tx;
        vh[oi] = th[tx][ty + 8*i]; vl[oi] = tl[tx][ty + 8*i];
    }
}

// ---------------- LN: single-pass (sum + sumsq) ----------------
template <int SPLIT>
__global__ void ln_kernel(const float* __restrict__ x, const float* __restrict__ w,
                          const float* __restrict__ bb, float* __restrict__ of,
                          __half* __restrict__ oh, __half* __restrict__ ol){
    __shared__ float red1[8], red2[8];
    const int row = blockIdx.x, t = threadIdx.x;
    const float* xp = x + (long)row * NDIM;
    float v0 = xp[t], v1 = xp[t+256], v2 = xp[t+512];
    float s1 = v0 + v1 + v2;
    float s2 = v0*v0 + v1*v1 + v2*v2;
#pragma unroll
    for (int o = 16; o; o >>= 1) {
        s1 += __shfl_xor_sync(~0u, s1, o);
        s2 += __shfl_xor_sync(~0u, s2, o);
    }
    if ((t & 31) == 0) { red1[t >> 5] = s1; red2[t >> 5] = s2; }
    __syncthreads();
    if (t < 32) {
        float r1 = (t < 8) ? red1[t] : 0.0f;
        float r2 = (t < 8) ? red2[t] : 0.0f;
#pragma unroll
        for (int o = 4; o; o >>= 1) {
            r1 += __shfl_xor_sync(~0u, r1, o);
            r2 += __shfl_xor_sync(~0u, r2, o);
        }
        if (t == 0) { red1[0] = r1; red2[0] = r2; }
    }
    __syncthreads();
    float mean = red1[0] * (1.0f / NDIM);
    float var  = red2[0] * (1.0f / NDIM) - mean * mean;
    float rs = rsqrtf(var + 1e-5f);
    float y0 = (v0-mean)*rs*w[t]     + bb[t];
    float y1 = (v1-mean)*rs*w[t+256] + bb[t+256];
    float y2 = (v2-mean)*rs*w[t+512] + bb[t+512];
    long o0 = (long)row * NDIM;
    if (SPLIT) {
        __half h, l;
        split2h(y0,h,l); oh[o0+t]=h;     ol[o0+t]=l;
        split2h(y1,h,l); oh[o0+t+256]=h; ol[o0+t+256]=l;
        split2h(y2,h,l); oh[o0+t+512]=h; ol[o0+t+512]=l;
    } else {
        of[o0+t]=y0; of[o0+t+256]=y1; of[o0+t+512]=y2;
    }
}

// ---------------- softmax (fp32 scores -> fp16 hi/lo P) ----------------
__global__ void softmax_split(const float* __restrict__ sc,
                              __half* __restrict__ ph, __half* __restrict__ pl){
    __shared__ float redm[4], reds[4];
    long rb = (long)blockIdx.x * NTOK;
    const int t = threadIdx.x;
    float4 v = *reinterpret_cast<const float4*>(&sc[rb + t*4]);
    float m = fmaxf(fmaxf(v.x, v.y), fmaxf(v.z, v.w));
#pragma unroll
    for (int o = 16; o; o >>= 1) m = fmaxf(m, __shfl_xor_sync(~0u, m, o));
    if ((t & 31) == 0) redm[t >> 5] = m;
    __syncthreads();
    m = fmaxf(fmaxf(redm[0], redm[1]), fmaxf(redm[2], redm[3]));
    v.x = __expf(v.x-m); v.y = __expf(v.y-m); v.z = __expf(v.z-m); v.w = __expf(v.w-m);
    float s = v.x + v.y + v.z + v.w;
#pragma unroll
    for (int o = 16; o; o >>= 1) s += __shfl_xor_sync(~0u, s, o);
    if ((t & 31) == 0) reds[t >> 5] = s;
    __syncthreads();
    s = reds[0] + reds[1] + reds[2] + reds[3];
    float inv = 1.0f / s;
    __half h0,l0,h1,l1,h2,l2,h3,l3;
    split2h(v.x*inv,h0,l0); split2h(v.y*inv,h1,l1); split2h(v.z*inv,h2,l2); split2h(v.w*inv,h3,l3);
    long off = rb + t*4;
    reinterpret_cast<__half2*>(ph+off)[0] = __halves2half2(h0,h1);
    reinterpret_cast<__half2*>(ph+off)[1] = __halves2half2(h2,h3);
    reinterpret_cast<__half2*>(pl+off)[0] = __halves2half2(l0,l1);
    reinterpret_cast<__half2*>(pl+off)[1] = __halves2half2(l2,l3);
}

// ---------------- split-fp16 GEMM via mma.sync ----------------
// C[M,N] = A[M,K] @ B[N,K]^T. A always split (ah+al exact); B single fp16 (BSPL=0)
// or split (BSPL=1, adds ah*bl term). 3-stage cp.async ring.
template <int BM, int BN, int BSPL>
__device__ __forceinline__ void ld_stage(uint32_t sb, int tid,
    const __half* pAh, const __half* pAl,
    const __half* pBh, const __half* pBl,
    long long lda, long long ldb, int row0, int col0, int k0){
    constexpr int ASZ = BM*80, BSZ2 = BN*80;
#pragma unroll
    for (int i = 0; i < BM/64; i++) {
        int ch = tid + i*256;
        int r = ch >> 2, c = ch & 3;
        uint32_t so = r*80 + c*16;
        long long go = (long long)(row0 + r) * lda + k0 + c*8;
        CPA16(sb + so, pAh + go);
        CPA16(sb + ASZ + so, pAl + go);
    }
#pragma unroll
    for (int i = 0; i < BN/64; i++) {
        int ch = tid + i*256;
        int r = ch >> 2, c = ch & 3;
        uint32_t so = r*80 + c*16;
        long long go = (long long)(col0 + r) * ldb + k0 + c*8;
        CPA16(sb + 2*ASZ + so, pBh + go);
        if (BSPL) CPA16(sb + 2*ASZ + BSZ2 + so, pBl + go);
    }
}

template <int BM, int BN, int EPI, int OCC, int BSPL>
__global__ void __launch_bounds__(256, OCC) mma_gemm(
    const __half* __restrict__ Ah, const __half* __restrict__ Al,
    long long lda, long long aSB, long long aSH,
    const __half* __restrict__ Bh, const __half* __restrict__ Bl,
    long long ldb, long long bSB, long long bSH,
    float* __restrict__ Cf, __half* __restrict__ Oh, __half* __restrict__ Ol,
    long long ldc, long long cSB, long long cSH,
    const float* __restrict__ bias, const float* __restrict__ pos,
    float scale, int K, int heads)
{
    extern __shared__ __align__(128) char smem_raw[];
    uint32_t sb = smem_u32(smem_raw);
    constexpr int ASZ = BM*80, BSZ2 = BN*80;
    constexpr int BUF = 2*ASZ + (1+BSPL)*BSZ2;
    constexpr int MW = BM/32;
    constexpr int NW = 8/MW;
    constexpr int WN = BN/NW;
    constexpr int NP = WN/16;
    constexpr int NT = WN/8;

    const int tid = threadIdx.x, lane = tid & 31, warp = tid >> 5;
    const int warpM = warp % MW, warpN = warp / MW;
    const int z = blockIdx.z, zb = z / heads, zh = z % heads;
    const __half* pAh = Ah + zb*aSB + zh*aSH;
    const __half* pAl = Al + zb*aSB + zh*aSH;
    const __half* pBh = Bh + zb*bSB + zh*bSH;
    const __half* pBl = BSPL ? (Bl + zb*bSB + zh*bSH) : pBh;
    const long long cOff = zb*cSB + zh*cSH;
    const int row0 = blockIdx.y * BM, col0 = blockIdx.x * BN;

    float acc[2][NT][4];
#pragma unroll
    for (int a = 0; a < 2; a++)
#pragma unroll
        for (int b = 0; b < NT; b++)
#pragma unroll
            for (int c = 0; c < 4; c++) acc[a][b][c] = 0.0f;

    const int nst = K >> 5;
    ld_stage<BM,BN,BSPL>(sb, tid, pAh, pAl, pBh, pBl, lda, ldb, row0, col0, 0);
    CP_COMMIT();
    if (nst > 1) {
        ld_stage<BM,BN,BSPL>(sb + BUF, tid, pAh, pAl, pBh, pBl, lda, ldb, row0, col0, 32);
        CP_COMMIT();
    }

    const int L = lane & 7, jj = lane >> 3;
    for (int st = 0; st < nst; st++) {
        if (st < nst - 1) CP_WAIT1(); else CP_WAIT0();
        __syncthreads();
        if (st + 2 < nst) {
            ld_stage<BM,BN,BSPL>(sb + ((st+2)%3)*BUF, tid, pAh, pAl, pBh, pBl,
                                 lda, ldb, row0, col0, (st+2)*32);
            CP_COMMIT();
        }
        uint32_t base = sb + (st % 3) * BUF;
#pragma unroll
        for (int ks = 0; ks < 2; ks++) {
            uint32_t ah_[2][4], al_[2][4];
#pragma unroll
            for (int mi = 0; mi < 2; mi++) {
                int mrow = warpM*32 + mi*16 + (jj & 1)*8 + L;
                int kcol = ks*16 + (jj >> 1)*8;
                uint32_t ad = base + mrow*80 + kcol*2;
                ldm4(ad, ah_[mi]);
                ldm4(ad + ASZ, al_[mi]);
            }
            uint32_t bh_[NP][4], bl_[NP][4];
#pragma unroll
            for (int np = 0; np < NP; np++) {
                int nrow = warpN*WN + np*16 + (jj >> 1)*8 + L;
                int kcol = ks*16 + (jj & 1)*8;
                uint32_t bd = base + 2*ASZ + nrow*80 + kcol*2;
                ldm4(bd, bh_[np]);
                if (BSPL) ldm4(bd + BSZ2, bl_[np]);
            }
#pragma unroll
            for (int mi = 0; mi < 2; mi++)
#pragma unroll
                for (int np = 0; np < NP; np++)
#pragma unroll
                    for (int si = 0; si < 2; si++) {
                        uint32_t fh[2] = { bh_[np][si*2], bh_[np][si*2+1] };
                        float* c = acc[mi][np*2 + si];
                        mma16816(c, ah_[mi], fh);
                        mma16816(c, al_[mi], fh);
                        if (BSPL) {
                            uint32_t fl[2] = { bl_[np][si*2], bl_[np][si*2+1] };
                            mma16816(c, ah_[mi], fl);
                        }
                    }
        }
    }

#pragma unroll
    for (int mi = 0; mi < 2; mi++)
#pragma unroll
        for (int nt = 0; nt < NT; nt++) {
            float* c = acc[mi][nt];
            int col = col0 + warpN*WN + nt*8 + (lane & 3)*2;
#pragma unroll
            for (int hf = 0; hf < 2; hf++) {
                int row = row0 + warpM*32 + mi*16 + (lane >> 2) + hf*8;
                float v0 = c[hf*2 + 0], v1 = c[hf*2 + 1];
                if (EPI == 0) {
                    float2* cp = reinterpret_cast<float2*>(Cf + cOff + (long long)row*ldc + col);
                    *cp = make_float2(v0*scale, v1*scale);
                } else if (EPI == 1) {
                    float2* cp = reinterpret_cast<float2*>(Cf + cOff + (long long)row*ldc + col);
                    float2 old = *cp;
                    *cp = make_float2(old.x + v0 + bias[col], old.y + v1 + bias[col+1]);
                } else if (EPI == 3) {
                    const float2* pp = reinterpret_cast<const float2*>(
                        pos + (long long)(row & (NTOK-1))*ldc + col);
                    float2 pv = *pp;
                    float2* cp = reinterpret_cast<float2*>(Cf + (long long)row*ldc + col);
                    *cp = make_float2(v0 + bias[col] + pv.x, v1 + bias[col+1] + pv.y);
                } else {
                    if (EPI == 2) {
                        v0 = tanhf(v0 + bias[col]);
                        v1 = tanhf(v1 + bias[col+1]);
                    }
                    __half h0, l0, h1, l1;
                    split2h(v0, h0, l0); split2h(v1, h1, l1);
                    long long off = cOff + (long long)row*ldc + col;
                    *reinterpret_cast<__half2*>(Oh + off) = __halves2half2(h0, h1);
                    *reinterpret_cast<__half2*>(Ol + off) = __halves2half2(l0, l1);
                }
            }
        }
}

// ---------------- host ----------------
extern "C" void kernel_launch(void* const* d_in, const int* in_sizes, int n_in,
                              void* d_out, int out_size)
{
    const float* volume    = (const float*)d_in[0];
    const float* conv_w    = (const float*)d_in[1];
    const float* conv_b    = (const float*)d_in[2];
    const float* pos_embed = (const float*)d_in[3];
    const float* ln1_w     = (const float*)d_in[4];
    const float* ln1_b     = (const float*)d_in[5];
    const float* w_qkv     = (const float*)d_in[6];
    const float* w_o       = (const float*)d_in[7];
    const float* b_o       = (const float*)d_in[8];
    const float* ln2_w     = (const float*)d_in[9];
    const float* ln2_b     = (const float*)d_in[10];
    const float* w1        = (const float*)d_in[11];
    const float* b1        = (const float*)d_in[12];
    const float* w2        = (const float*)d_in[13];
    const float* b2        = (const float*)d_in[14];
    const float* lnf_w     = (const float*)d_in[15];
    const float* lnf_b     = (const float*)d_in[16];
    float* out = (float*)d_out;

    __half *pat_h,*pat_l,*cw,*wqT,*woT,*w1T,*w2T,*h_h,*h_l,*qkv_h,*qkv_l;
    __half *p_h,*p_l,*vt_h,*vt_l,*o_h,*o_l,*m_h,*m_l;
    float *x, *scores;
    cudaGetSymbolAddress((void**)&pat_h, g_pat_h); cudaGetSymbolAddress((void**)&pat_l, g_pat_l);
    cudaGetSymbolAddress((void**)&cw, g_cw);
    cudaGetSymbolAddress((void**)&wqT, g_wqkvT);
    cudaGetSymbolAddress((void**)&woT, g_woT);
    cudaGetSymbolAddress((void**)&w1T, g_w1T);
    cudaGetSymbolAddress((void**)&w2T, g_w2T);
    cudaGetSymbolAddress((void**)&x, g_x);
    cudaGetSymbolAddress((void**)&h_h, g_h_h);     cudaGetSymbolAddress((void**)&h_l, g_h_l);
    cudaGetSymbolAddress((void**)&qkv_h, g_qkv_h); cudaGetSymbolAddress((void**)&qkv_l, g_qkv_l);
    cudaGetSymbolAddress((void**)&scores, g_scores);
    cudaGetSymbolAddress((void**)&p_h, g_p_h);     cudaGetSymbolAddress((void**)&p_l, g_p_l);
    cudaGetSymbolAddress((void**)&vt_h, g_vt_h);   cudaGetSymbolAddress((void**)&vt_l, g_vt_l);
    cudaGetSymbolAddress((void**)&o_h, g_o_h);     cudaGetSymbolAddress((void**)&o_l, g_o_l);
    cudaGetSymbolAddress((void**)&m_h, g_m_h);     cudaGetSymbolAddress((void**)&m_l, g_m_l);

    const int S_QKV  = 3*(2*128*80 + 1*128*80);   // 92160
    const int S_QK   = 3*(2*128*80 + 2*128*80);   // 122880
    const int S_PV   = 3*(2*64*80  + 2*64*80);    // 61440
    const int S_6464 = 3*(2*64*80  + 1*64*80);    // 46080
    const int S_MLP1 = 3*(2*128*80 + 1*192*80);   // 107520
    cudaFuncSetAttribute((const void*)mma_gemm<128,128,4,1,0>, cudaFuncAttributeMaxDynamicSharedMemorySize, S_QKV);
    cudaFuncSetAttribute((const void*)mma_gemm<128,128,0,1,1>, cudaFuncAttributeMaxDynamicSharedMemorySize, S_QK);
    cudaFuncSetAttribute((const void*)mma_gemm<64,64,4,2,1>,   cudaFuncAttributeMaxDynamicSharedMemorySize, S_PV);
    cudaFuncSetAttribute((const void*)mma_gemm<64,64,1,2,0>,   cudaFuncAttributeMaxDynamicSharedMemorySize, S_6464);
    cudaFuncSetAttribute((const void*)mma_gemm<64,64,3,2,0>,   cudaFuncAttributeMaxDynamicSharedMemorySize, S_6464);
    cudaFuncSetAttribute((const void*)mma_gemm<128,192,2,1,0>, cudaFuncAttributeMaxDynamicSharedMemorySize, S_MLP1);

    dim3 tb(32, 8);

    im2col_split<<<(MALL*PATCHES)/256, 256>>>(volume, pat_h, pat_l);
    conv_half<<<(NDIM*PATCHES)/256, 256>>>(conv_w, cw, NDIM*PATCHES);
    wt_half<<<dim3(QKVW/32, NDIM/32, NDEPTH), tb>>>(w_qkv, wqT, NDIM, QKVW);
    wt_half<<<dim3(NDIM/32, NDIM/32, NDEPTH), tb>>>(w_o, woT, NDIM, NDIM);
    wt_half<<<dim3(DMLP/32, NDIM/32, NDEPTH), tb>>>(w1, w1T, NDIM, DMLP);
    wt_half<<<dim3(NDIM/32, DMLP/32, NDEPTH), tb>>>(w2, w2T, DMLP, NDIM);

    // patch embed: x = patches @ conv_w^T + conv_b + pos
    mma_gemm<64,64,3,2,0><<<dim3(NDIM/64, MALL/64, 1), 256, S_6464>>>(
        pat_h, pat_l, PATCHES, 0, 0, cw, cw, PATCHES, 0, 0,
        x, nullptr, nullptr, NDIM, 0, 0, conv_b, pos_embed, 1.f, PATCHES, 1);

    for (int l = 0; l < NDEPTH; ++l) {
        ln_kernel<1><<<MALL, 256>>>(x, ln1_w + l*NDIM, ln1_b + l*NDIM, nullptr, h_h, h_l);
        mma_gemm<128,128,4,1,0><<<dim3(QKVW/128, MALL/128, 1), 256, S_QKV>>>(
            h_h, h_l, NDIM, 0, 0, wqT + (long)l*QKVW*NDIM, nullptr, NDIM, 0, 0,
            nullptr, qkv_h, qkv_l, QKVW, 0, 0, nullptr, nullptr, 1.f, NDIM, 1);
        mma_gemm<128,128,0,1,1><<<dim3(NTOK/128, NTOK/128, NBH), 256, S_QK>>>(
            qkv_h, qkv_l, QKVW, (long long)NTOK*QKVW, DHEAD,
            qkv_h + NDIM, qkv_l + NDIM, QKVW, (long long)NTOK*QKVW, DHEAD,
            scores, nullptr, nullptr, NTOK, (long long)NHEADS*NTOK*NTOK, (long long)NTOK*NTOK,
            nullptr, nullptr, 0.125f, DHEAD, NHEADS);
        softmax_split<<<NBH*NTOK, 128>>>(scores, p_h, p_l);
        vt_split<<<dim3(NTOK/32, DHEAD/32, NBH), tb>>>(qkv_h, qkv_l, vt_h, vt_l);
        mma_gemm<64,64,4,2,1><<<dim3(1, NTOK/64, NBH), 256, S_PV>>>(
            p_h, p_l, NTOK, (long long)NHEADS*NTOK*NTOK, (long long)NTOK*NTOK,
            vt_h, vt_l, NTOK, (long long)NHEADS*DHEAD*NTOK, (long long)DHEAD*NTOK,
            nullptr, o_h, o_l, NDIM, (long long)NTOK*NDIM, DHEAD,
            nullptr, nullptr, 1.f, NTOK, NHEADS);
        mma_gemm<64,64,1,2,0><<<dim3(NDIM/64, MALL/64, 1), 256, S_6464>>>(
            o_h, o_l, NDIM, 0, 0, woT + (long)l*NDIM*NDIM, nullptr, NDIM, 0, 0,
            x, nullptr, nullptr, NDIM, 0, 0, b_o + l*NDIM, nullptr, 1.f, NDIM, 1);
        ln_kernel<1><<<MALL, 256>>>(x, ln2_w + l*NDIM, ln2_b + l*NDIM, nullptr, h_h, h_l);
        mma_gemm<128,192,2,1,0><<<dim3(DMLP/192, MALL/128, 1), 256, S_MLP1>>>(
            h_h, h_l, NDIM, 0, 0, w1T + (long)l*DMLP*NDIM, nullptr, NDIM, 0, 0,
            nullptr, m_h, m_l, DMLP, 0, 0, b1 + l*DMLP, nullptr, 1.f, NDIM, 1);
        mma_gemm<64,64,1,2,0><<<dim3(NDIM/64, MALL/64, 1), 256, S_6464>>>(
            m_h, m_l, DMLP, 0, 0, w2T + (long)l*NDIM*DMLP, nullptr, DMLP, 0, 0,
            x, nullptr, nullptr, NDIM, 0, 0, b2 + l*NDIM, nullptr, 1.f, DMLP, 1);
    }

    ln_kernel<0><<<MALL, 256>>>(x, lnf_w, lnf_b, out, nullptr, nullptr);
}

// round 9
// speedup vs baseline: 1.9393x; 1.0488x over previous
#include <cuda_runtime.h>
#include <cuda_fp16.h>
#include <cstdint>
#include <math.h>

#define NDIM 768
#define NTOK 512
#define BSZ 2
#define MALL 1024
#define NHEADS 12
#define DHEAD 64
#define DMLP 3072
#define NDEPTH 4
#define QKVW 2304
#define PATCHES 512
#define NBH (BSZ*NHEADS)

__device__ __forceinline__ uint32_t smem_u32(const void* p){
    uint32_t a;
    asm("{ .reg .u64 t; cvta.to.shared.u64 t, %1; cvt.u32.u64 %0, t; }" : "=r"(a) : "l"(p));
    return a;
}
#define CPA16(d, s) asm volatile("cp.async.cg.shared.global [%0], [%1], 16;" :: "r"(d), "l"(s))
#define CP_COMMIT() asm volatile("cp.async.commit_group;" ::: "memory")
#define CP_WAIT1()  asm volatile("cp.async.wait_group 1;" ::: "memory")
#define CP_WAIT0()  asm volatile("cp.async.wait_group 0;" ::: "memory")

__device__ __forceinline__ void ldm4(uint32_t addr, uint32_t* r){
    asm volatile("ldmatrix.sync.aligned.m8n8.x4.shared.b16 {%0,%1,%2,%3}, [%4];"
        : "=r"(r[0]), "=r"(r[1]), "=r"(r[2]), "=r"(r[3]) : "r"(addr));
}
__device__ __forceinline__ void mma16816(float* c, const uint32_t* a, const uint32_t* b){
    asm volatile("mma.sync.aligned.m16n8k16.row.col.f32.f16.f16.f32 "
        "{%0,%1,%2,%3}, {%4,%5,%6,%7}, {%8,%9}, {%0,%1,%2,%3};"
        : "+f"(c[0]), "+f"(c[1]), "+f"(c[2]), "+f"(c[3])
        : "r"(a[0]), "r"(a[1]), "r"(a[2]), "r"(a[3]), "r"(b[0]), "r"(b[1]));
}
__device__ __forceinline__ void split2h(float v, __half& h, __half& l){
    h = __float2half_rn(v);
    l = __float2half_rn(v - __half2float(h));
}

// ---------------- scratch ----------------
__device__ __align__(256) __half g_pat_h[MALL*PATCHES], g_pat_l[MALL*PATCHES];
__device__ __align__(256) __half g_cw[NDIM*PATCHES];
__device__ __align__(256) __half g_wqkvT[NDEPTH*QKVW*NDIM];
__device__ __align__(256) __half g_woT[NDEPTH*NDIM*NDIM];
__device__ __align__(256) __half g_w1T[NDEPTH*DMLP*NDIM];
__device__ __align__(256) __half g_w2T[NDEPTH*NDIM*DMLP];
__device__ __align__(256) float  g_x[MALL*NDIM];
__device__ __align__(256) __half g_h_h[MALL*NDIM], g_h_l[MALL*NDIM];
__device__ __align__(256) __half g_qkv_h[MALL*QKVW], g_qkv_l[MALL*QKVW];
__device__ __align__(256) float  g_scores[NBH*NTOK*NTOK];
__device__ __align__(256) __half g_p_h[NBH*NTOK*NTOK], g_p_l[NBH*NTOK*NTOK];
__device__ __align__(256) __half g_vt_h[NBH*DHEAD*NTOK];
__device__ __align__(256) __half g_o_h[MALL*NDIM], g_o_l[MALL*NDIM];
__device__ __align__(256) __half g_m_h[MALL*DMLP], g_m_l[MALL*DMLP];

// ---------------- prep kernels ----------------
__global__ void im2col_split(const float* __restrict__ vol,
                             __half* __restrict__ oh, __half* __restrict__ ol){
    int idx = blockIdx.x * 256 + threadIdx.x;
    int m = idx & 511, tkn = idx >> 9, n = tkn & 511, b = tkn >> 9;
    int k = m & 7, j = (m >> 3) & 7, i = m >> 6;
    int pw = n & 7, ph = (n >> 3) & 7, pd = n >> 6;
    float v = vol[((long)b << 18) + (pd*8+i)*4096 + (ph*8+j)*64 + (pw*8+k)];
    __half h, l; split2h(v, h, l);
    oh[idx] = h; ol[idx] = l;
}
__global__ void conv_half(const float* __restrict__ in, __half* __restrict__ o, int n){
    int idx = blockIdx.x * 256 + threadIdx.x;
    if (idx >= n) return;
    o[idx] = __float2half_rn(in[idx]);
}
// transpose+convert: in fp32 [L][R][C] -> out fp16 [L][C][R]
__global__ void wt_half(const float* __restrict__ in, __half* __restrict__ o, int R, int C){
    __shared__ float tf[32][33];
    int z = blockIdx.z;
    const float* ip = in + (long)z * R * C;
    int r0 = blockIdx.y * 32, c0 = blockIdx.x * 32;
    int tx = threadIdx.x, ty = threadIdx.y;
#pragma unroll
    for (int i = 0; i < 4; i++)
        tf[ty + 8*i][tx] = ip[(long)(r0 + ty + 8*i) * C + c0 + tx];
    __syncthreads();
    long ob = (long)z * R * C;
#pragma unroll
    for (int i = 0; i < 4; i++)
        o[ob + (long)(c0 + ty + 8*i) * R + r0 + tx] = __float2half_rn(tf[tx][ty + 8*i]);
}

// ---------------- LN: single-pass (sum + sumsq) ----------------
template <int SPLIT>
__global__ void ln_kernel(const float* __restrict__ x, const float* __restrict__ w,
                          const float* __restrict__ bb, float* __restrict__ of,
                          __half* __restrict__ oh, __half* __restrict__ ol){
    __shared__ float red1[8], red2[8];
    const int row = blockIdx.x, t = threadIdx.x;
    const float* xp = x + (long)row * NDIM;
    float v0 = xp[t], v1 = xp[t+256], v2 = xp[t+512];
    float s1 = v0 + v1 + v2;
    float s2 = v0*v0 + v1*v1 + v2*v2;
#pragma unroll
    for (int o = 16; o; o >>= 1) {
        s1 += __shfl_xor_sync(~0u, s1, o);
        s2 += __shfl_xor_sync(~0u, s2, o);
    }
    if ((t & 31) == 0) { red1[t >> 5] = s1; red2[t >> 5] = s2; }
    __syncthreads();
    if (t < 32) {
        float r1 = (t < 8) ? red1[t] : 0.0f;
        float r2 = (t < 8) ? red2[t] : 0.0f;
#pragma unroll
        for (int o = 4; o; o >>= 1) {
            r1 += __shfl_xor_sync(~0u, r1, o);
            r2 += __shfl_xor_sync(~0u, r2, o);
        }
        if (t == 0) { red1[0] = r1; red2[0] = r2; }
    }
    __syncthreads();
    float mean = red1[0] * (1.0f / NDIM);
    float var  = red2[0] * (1.0f / NDIM) - mean * mean;
    float rs = rsqrtf(var + 1e-5f);
    float y0 = (v0-mean)*rs*w[t]     + bb[t];
    float y1 = (v1-mean)*rs*w[t+256] + bb[t+256];
    float y2 = (v2-mean)*rs*w[t+512] + bb[t+512];
    long o0 = (long)row * NDIM;
    if (SPLIT) {
        __half h, l;
        split2h(y0,h,l); oh[o0+t]=h;     ol[o0+t]=l;
        split2h(y1,h,l); oh[o0+t+256]=h; ol[o0+t+256]=l;
        split2h(y2,h,l); oh[o0+t+512]=h; ol[o0+t+512]=l;
    } else {
        of[o0+t]=y0; of[o0+t+256]=y1; of[o0+t+512]=y2;
    }
}

// ---------------- softmax (fp32 scores -> fp16 hi/lo P) ----------------
__global__ void softmax_split(const float* __restrict__ sc,
                              __half* __restrict__ ph, __half* __restrict__ pl){
    __shared__ float redm[4], reds[4];
    long rb = (long)blockIdx.x * NTOK;
    const int t = threadIdx.x;
    float4 v = *reinterpret_cast<const float4*>(&sc[rb + t*4]);
    float m = fmaxf(fmaxf(v.x, v.y), fmaxf(v.z, v.w));
#pragma unroll
    for (int o = 16; o; o >>= 1) m = fmaxf(m, __shfl_xor_sync(~0u, m, o));
    if ((t & 31) == 0) redm[t >> 5] = m;
    __syncthreads();
    m = fmaxf(fmaxf(redm[0], redm[1]), fmaxf(redm[2], redm[3]));
    v.x = __expf(v.x-m); v.y = __expf(v.y-m); v.z = __expf(v.z-m); v.w = __expf(v.w-m);
    float s = v.x + v.y + v.z + v.w;
#pragma unroll
    for (int o = 16; o; o >>= 1) s += __shfl_xor_sync(~0u, s, o);
    if ((t & 31) == 0) reds[t >> 5] = s;
    __syncthreads();
    s = reds[0] + reds[1] + reds[2] + reds[3];
    float inv = 1.0f / s;
    __half h0,l0,h1,l1,h2,l2,h3,l3;
    split2h(v.x*inv,h0,l0); split2h(v.y*inv,h1,l1); split2h(v.z*inv,h2,l2); split2h(v.w*inv,h3,l3);
    long off = rb + t*4;
    reinterpret_cast<__half2*>(ph+off)[0] = __halves2half2(h0,h1);
    reinterpret_cast<__half2*>(ph+off)[1] = __halves2half2(h2,h3);
    reinterpret_cast<__half2*>(pl+off)[0] = __halves2half2(l0,l1);
    reinterpret_cast<__half2*>(pl+off)[1] = __halves2half2(l2,l3);
}

// ---------------- split-fp16 GEMM via mma.sync ----------------
// C[M,N] = A[M,K] @ B[N,K]^T. A split (exact); B single fp16 (BSPL=0) or split (BSPL=1).
// EPI: 0 fp32*scale | 1 fp32 residual+=acc+bias | 2 tanh(acc+bias)->split
//      3 acc+bias+pos->fp32 | 4 acc->split | 5 qkv fused (Q split, K hi, V->vt transposed)
template <int BM, int BN, int BSPL>
__device__ __forceinline__ void ld_stage(uint32_t sb, int tid,
    const __half* pAh, const __half* pAl,
    const __half* pBh, const __half* pBl,
    long long lda, long long ldb, int row0, int col0, int k0){
    constexpr int ASZ = BM*80, BSZ2 = BN*80;
#pragma unroll
    for (int i = 0; i < BM/64; i++) {
        int ch = tid + i*256;
        int r = ch >> 2, c = ch & 3;
        uint32_t so = r*80 + c*16;
        long long go = (long long)(row0 + r) * lda + k0 + c*8;
        CPA16(sb + so, pAh + go);
        CPA16(sb + ASZ + so, pAl + go);
    }
#pragma unroll
    for (int i = 0; i < BN/64; i++) {
        int ch = tid + i*256;
        int r = ch >> 2, c = ch & 3;
        uint32_t so = r*80 + c*16;
        long long go = (long long)(col0 + r) * ldb + k0 + c*8;
        CPA16(sb + 2*ASZ + so, pBh + go);
        if (BSPL) CPA16(sb + 2*ASZ + BSZ2 + so, pBl + go);
    }
}

template <int BM, int BN, int EPI, int OCC, int BSPL>
__global__ void __launch_bounds__(256, OCC) mma_gemm(
    const __half* __restrict__ Ah, const __half* __restrict__ Al,
    long long lda, long long aSB, long long aSH,
    const __half* __restrict__ Bh, const __half* __restrict__ Bl,
    long long ldb, long long bSB, long long bSH,
    float* __restrict__ Cf, __half* __restrict__ Oh, __half* __restrict__ Ol,
    __half* __restrict__ Vt,
    long long ldc, long long cSB, long long cSH,
    const float* __restrict__ bias, const float* __restrict__ pos,
    float scale, int K, int heads)
{
    extern __shared__ __align__(128) char smem_raw[];
    uint32_t sb = smem_u32(smem_raw);
    constexpr int ASZ = BM*80, BSZ2 = BN*80;
    constexpr int BUF = 2*ASZ + (1+BSPL)*BSZ2;
    constexpr int MW = BM/32;
    constexpr int NW = 8/MW;
    constexpr int WN = BN/NW;
    constexpr int NP = WN/16;
    constexpr int NT = WN/8;

    const int tid = threadIdx.x, lane = tid & 31, warp = tid >> 5;
    const int warpM = warp % MW, warpN = warp / MW;
    const int z = blockIdx.z, zb = z / heads, zh = z % heads;
    const __half* pAh = Ah + zb*aSB + zh*aSH;
    const __half* pAl = Al + zb*aSB + zh*aSH;
    const __half* pBh = Bh + zb*bSB + zh*bSH;
    const __half* pBl = BSPL ? (Bl + zb*bSB + zh*bSH) : pBh;
    const long long cOff = zb*cSB + zh*cSH;
    const int row0 = blockIdx.y * BM, col0 = blockIdx.x * BN;

    float acc[2][NT][4];
#pragma unroll
    for (int a = 0; a < 2; a++)
#pragma unroll
        for (int b = 0; b < NT; b++)
#pragma unroll
            for (int c = 0; c < 4; c++) acc[a][b][c] = 0.0f;

    const int nst = K >> 5;
    ld_stage<BM,BN,BSPL>(sb, tid, pAh, pAl, pBh, pBl, lda, ldb, row0, col0, 0);
    CP_COMMIT();
    if (nst > 1) {
        ld_stage<BM,BN,BSPL>(sb + BUF, tid, pAh, pAl, pBh, pBl, lda, ldb, row0, col0, 32);
        CP_COMMIT();
    }

    const int L = lane & 7, jj = lane >> 3;
    for (int st = 0; st < nst; st++) {
        if (st < nst - 1) CP_WAIT1(); else CP_WAIT0();
        __syncthreads();
        if (st + 2 < nst) {
            ld_stage<BM,BN,BSPL>(sb + ((st+2)%3)*BUF, tid, pAh, pAl, pBh, pBl,
                                 lda, ldb, row0, col0, (st+2)*32);
            CP_COMMIT();
        }
        uint32_t base = sb + (st % 3) * BUF;
#pragma unroll
        for (int ks = 0; ks < 2; ks++) {
            uint32_t ah_[2][4], al_[2][4];
#pragma unroll
            for (int mi = 0; mi < 2; mi++) {
                int mrow = warpM*32 + mi*16 + (jj & 1)*8 + L;
                int kcol = ks*16 + (jj >> 1)*8;
                uint32_t ad = base + mrow*80 + kcol*2;
                ldm4(ad, ah_[mi]);
                ldm4(ad + ASZ, al_[mi]);
            }
            uint32_t bh_[NP][4], bl_[NP][4];
#pragma unroll
            for (int np = 0; np < NP; np++) {
                int nrow = warpN*WN + np*16 + (jj >> 1)*8 + L;
                int kcol = ks*16 + (jj & 1)*8;
                uint32_t bd = base + 2*ASZ + nrow*80 + kcol*2;
                ldm4(bd, bh_[np]);
                if (BSPL) ldm4(bd + BSZ2, bl_[np]);
            }
#pragma unroll
            for (int mi = 0; mi < 2; mi++)
#pragma unroll
                for (int np = 0; np < NP; np++)
#pragma unroll
                    for (int si = 0; si < 2; si++) {
                        uint32_t fh[2] = { bh_[np][si*2], bh_[np][si*2+1] };
                        float* c = acc[mi][np*2 + si];
                        mma16816(c, ah_[mi], fh);
                        mma16816(c, al_[mi], fh);
                        if (BSPL) {
                            uint32_t fl[2] = { bl_[np][si*2], bl_[np][si*2+1] };
                            mma16816(c, ah_[mi], fl);
                        }
                    }
        }
    }

#pragma unroll
    for (int mi = 0; mi < 2; mi++)
#pragma unroll
        for (int nt = 0; nt < NT; nt++) {
            float* c = acc[mi][nt];
            int col = col0 + warpN*WN + nt*8 + (lane & 3)*2;
#pragma unroll
            for (int hf = 0; hf < 2; hf++) {
                int row = row0 + warpM*32 + mi*16 + (lane >> 2) + hf*8;
                float v0 = c[hf*2 + 0], v1 = c[hf*2 + 1];
                if (EPI == 0) {
                    float2* cp = reinterpret_cast<float2*>(Cf + cOff + (long long)row*ldc + col);
                    *cp = make_float2(v0*scale, v1*scale);
                } else if (EPI == 1) {
                    float2* cp = reinterpret_cast<float2*>(Cf + cOff + (long long)row*ldc + col);
                    float2 old = *cp;
                    *cp = make_float2(old.x + v0 + bias[col], old.y + v1 + bias[col+1]);
                } else if (EPI == 3) {
                    const float2* pp = reinterpret_cast<const float2*>(
                        pos + (long long)(row & (NTOK-1))*ldc + col);
                    float2 pv = *pp;
                    float2* cp = reinterpret_cast<float2*>(Cf + (long long)row*ldc + col);
                    *cp = make_float2(v0 + bias[col] + pv.x, v1 + bias[col+1] + pv.y);
                } else if (EPI == 5) {
                    // QKV fused: Q cols split, K cols hi only, V cols -> transposed vt
                    if (col0 < NDIM) {
                        __half h0, l0, h1, l1;
                        split2h(v0, h0, l0); split2h(v1, h1, l1);
                        long long off = (long long)row*ldc + col;
                        *reinterpret_cast<__half2*>(Oh + off) = __halves2half2(h0, h1);
                        *reinterpret_cast<__half2*>(Ol + off) = __halves2half2(l0, l1);
                    } else if (col0 < 2*NDIM) {
                        long long off = (long long)row*ldc + col;
                        *reinterpret_cast<__half2*>(Oh + off) =
                            __halves2half2(__float2half_rn(v0), __float2half_rn(v1));
                    } else {
                        int bb2 = row >> 9, t2 = row & (NTOK-1);
                        int hd = col - 2*NDIM, hh2 = hd >> 6, d = hd & (DHEAD-1);
                        long vtb = ((long)(bb2*NHEADS + hh2)*DHEAD + d)*NTOK + t2;
                        Vt[vtb] = __float2half_rn(v0);
                        Vt[vtb + NTOK] = __float2half_rn(v1);
                    }
                } else {
                    if (EPI == 2) {
                        v0 = tanhf(v0 + bias[col]);
                        v1 = tanhf(v1 + bias[col+1]);
                    }
                    __half h0, l0, h1, l1;
                    split2h(v0, h0, l0); split2h(v1, h1, l1);
                    long long off = cOff + (long long)row*ldc + col;
                    *reinterpret_cast<__half2*>(Oh + off) = __halves2half2(h0, h1);
                    *reinterpret_cast<__half2*>(Ol + off) = __halves2half2(l0, l1);
                }
            }
        }
}

// ---------------- host ----------------
extern "C" void kernel_launch(void* const* d_in, const int* in_sizes, int n_in,
                              void* d_out, int out_size)
{
    const float* volume    = (const float*)d_in[0];
    const float* conv_w    = (const float*)d_in[1];
    const float* conv_b    = (const float*)d_in[2];
    const float* pos_embed = (const float*)d_in[3];
    const float* ln1_w     = (const float*)d_in[4];
    const float* ln1_b     = (const float*)d_in[5];
    const float* w_qkv     = (const float*)d_in[6];
    const float* w_o       = (const float*)d_in[7];
    const float* b_o       = (const float*)d_in[8];
    const float* ln2_w     = (const float*)d_in[9];
    const float* ln2_b     = (const float*)d_in[10];
    const float* w1        = (const float*)d_in[11];
    const float* b1        = (const float*)d_in[12];
    const float* w2        = (const float*)d_in[13];
    const float* b2        = (const float*)d_in[14];
    const float* lnf_w     = (const float*)d_in[15];
    const float* lnf_b     = (const float*)d_in[16];
    float* out = (float*)d_out;

    __half *pat_h,*pat_l,*cw,*wqT,*woT,*w1T,*w2T,*h_h,*h_l,*qkv_h,*qkv_l;
    __half *p_h,*p_l,*vt_h,*o_h,*o_l,*m_h,*m_l;
    float *x, *scores;
    cudaGetSymbolAddress((void**)&pat_h, g_pat_h); cudaGetSymbolAddress((void**)&pat_l, g_pat_l);
    cudaGetSymbolAddress((void**)&cw, g_cw);
    cudaGetSymbolAddress((void**)&wqT, g_wqkvT);
    cudaGetSymbolAddress((void**)&woT, g_woT);
    cudaGetSymbolAddress((void**)&w1T, g_w1T);
    cudaGetSymbolAddress((void**)&w2T, g_w2T);
    cudaGetSymbolAddress((void**)&x, g_x);
    cudaGetSymbolAddress((void**)&h_h, g_h_h);     cudaGetSymbolAddress((void**)&h_l, g_h_l);
    cudaGetSymbolAddress((void**)&qkv_h, g_qkv_h); cudaGetSymbolAddress((void**)&qkv_l, g_qkv_l);
    cudaGetSymbolAddress((void**)&scores, g_scores);
    cudaGetSymbolAddress((void**)&p_h, g_p_h);     cudaGetSymbolAddress((void**)&p_l, g_p_l);
    cudaGetSymbolAddress((void**)&vt_h, g_vt_h);
    cudaGetSymbolAddress((void**)&o_h, g_o_h);     cudaGetSymbolAddress((void**)&o_l, g_o_l);
    cudaGetSymbolAddress((void**)&m_h, g_m_h);     cudaGetSymbolAddress((void**)&m_l, g_m_l);

    const int S_QKV  = 3*(2*128*80 + 1*128*80);   // 92160
    const int S_QK   = 3*(2*128*80 + 1*128*80);   // 92160
    const int S_PV   = 3*(2*64*80  + 1*64*80);    // 46080
    const int S_6464 = 3*(2*64*80  + 1*64*80);    // 46080
    const int S_MLP1 = 3*(2*128*80 + 1*192*80);   // 107520
    cudaFuncSetAttribute((const void*)mma_gemm<128,128,5,1,0>, cudaFuncAttributeMaxDynamicSharedMemorySize, S_QKV);
    cudaFuncSetAttribute((const void*)mma_gemm<128,128,0,1,0>, cudaFuncAttributeMaxDynamicSharedMemorySize, S_QK);
    cudaFuncSetAttribute((const void*)mma_gemm<64,64,4,2,0>,   cudaFuncAttributeMaxDynamicSharedMemorySize, S_PV);
    cudaFuncSetAttribute((const void*)mma_gemm<64,64,1,2,0>,   cudaFuncAttributeMaxDynamicSharedMemorySize, S_6464);
    cudaFuncSetAttribute((const void*)mma_gemm<64,64,3,2,0>,   cudaFuncAttributeMaxDynamicSharedMemorySize, S_6464);
    cudaFuncSetAttribute((const void*)mma_gemm<128,192,2,1,0>, cudaFuncAttributeMaxDynamicSharedMemorySize, S_MLP1);

    dim3 tb(32, 8);

    im2col_split<<<(MALL*PATCHES)/256, 256>>>(volume, pat_h, pat_l);
    conv_half<<<(NDIM*PATCHES)/256, 256>>>(conv_w, cw, NDIM*PATCHES);
    wt_half<<<dim3(QKVW/32, NDIM/32, NDEPTH), tb>>>(w_qkv, wqT, NDIM, QKVW);
    wt_half<<<dim3(NDIM/32, NDIM/32, NDEPTH), tb>>>(w_o, woT, NDIM, NDIM);
    wt_half<<<dim3(DMLP/32, NDIM/32, NDEPTH), tb>>>(w1, w1T, NDIM, DMLP);
    wt_half<<<dim3(NDIM/32, DMLP/32, NDEPTH), tb>>>(w2, w2T, DMLP, NDIM);

    // patch embed: x = patches @ conv_w^T + conv_b + pos
    mma_gemm<64,64,3,2,0><<<dim3(NDIM/64, MALL/64, 1), 256, S_6464>>>(
        pat_h, pat_l, PATCHES, 0, 0, cw, cw, PATCHES, 0, 0,
        x, nullptr, nullptr, nullptr, NDIM, 0, 0, conv_b, pos_embed, 1.f, PATCHES, 1);

    for (int l = 0; l < NDEPTH; ++l) {
        ln_kernel<1><<<MALL, 256>>>(x, ln1_w + l*NDIM, ln1_b + l*NDIM, nullptr, h_h, h_l);
        // QKV fused epilogue: Q split, K hi, V transposed into vt_h
        mma_gemm<128,128,5,1,0><<<dim3(QKVW/128, MALL/128, 1), 256, S_QKV>>>(
            h_h, h_l, NDIM, 0, 0, wqT + (long)l*QKVW*NDIM, nullptr, NDIM, 0, 0,
            nullptr, qkv_h, qkv_l, vt_h, QKVW, 0, 0, nullptr, nullptr, 1.f, NDIM, 1);
        // QK: A = Q (split), B = K (hi only)
        mma_gemm<128,128,0,1,0><<<dim3(NTOK/128, NTOK/128, NBH), 256, S_QK>>>(
            qkv_h, qkv_l, QKVW, (long long)NTOK*QKVW, DHEAD,
            qkv_h + NDIM, nullptr, QKVW, (long long)NTOK*QKVW, DHEAD,
            scores, nullptr, nullptr, nullptr, NTOK, (long long)NHEADS*NTOK*NTOK, (long long)NTOK*NTOK,
            nullptr, nullptr, 0.125f, DHEAD, NHEADS);
        softmax_split<<<NBH*NTOK, 128>>>(scores, p_h, p_l);
        // PV: A = P (split), B = Vt (hi only)
        mma_gemm<64,64,4,2,0><<<dim3(1, NTOK/64, NBH), 256, S_PV>>>(
            p_h, p_l, NTOK, (long long)NHEADS*NTOK*NTOK, (long long)NTOK*NTOK,
            vt_h, nullptr, NTOK, (long long)NHEADS*DHEAD*NTOK, (long long)DHEAD*NTOK,
            nullptr, o_h, o_l, nullptr, NDIM, (long long)NTOK*NDIM, DHEAD,
            nullptr, nullptr, 1.f, NTOK, NHEADS);
        mma_gemm<64,64,1,2,0><<<dim3(NDIM/64, MALL/64, 1), 256, S_6464>>>(
            o_h, o_l, NDIM, 0, 0, woT + (long)l*NDIM*NDIM, nullptr, NDIM, 0, 0,
            x, nullptr, nullptr, nullptr, NDIM, 0, 0, b_o + l*NDIM, nullptr, 1.f, NDIM, 1);
        ln_kernel<1><<<MALL, 256>>>(x, ln2_w + l*NDIM, ln2_b + l*NDIM, nullptr, h_h, h_l);
        mma_gemm<128,192,2,1,0><<<dim3(DMLP/192, MALL/128, 1), 256, S_MLP1>>>(
            h_h, h_l, NDIM, 0, 0, w1T + (long)l*DMLP*NDIM, nullptr, NDIM, 0, 0,
            nullptr, m_h, m_l, nullptr, DMLP, 0, 0, b1 + l*DMLP, nullptr, 1.f, NDIM, 1);
        mma_gemm<64,64,1,2,0><<<dim3(NDIM/64, MALL/64, 1), 256, S_6464>>>(
            m_h, m_l, DMLP, 0, 0, w2T + (long)l*NDIM*DMLP, nullptr, DMLP, 0, 0,
            x, nullptr, nullptr, nullptr, NDIM, 0, 0, b2 + l*NDIM, nullptr, 1.f, DMLP, 1);
    }

    ln_kernel<0><<<MALL, 256>>>(x, lnf_w, lnf_b, out, nullptr, nullptr);
}

// round 10
// speedup vs baseline: 2.8407x; 1.4648x over previous
#include <cuda_runtime.h>
#include <cuda_fp16.h>
#include <cstdint>
#include <math.h>

#define NDIM 768
#define NTOK 512
#define BSZ 2
#define MALL 1024
#define NHEADS 12
#define DHEAD 64
#define DMLP 3072
#define NDEPTH 4
#define QKVW 2304
#define PATCHES 512
#define NBH (BSZ*NHEADS)

__device__ __forceinline__ uint32_t smem_u32(const void* p){
    uint32_t a;
    asm("{ .reg .u64 t; cvta.to.shared.u64 t, %1; cvt.u32.u64 %0, t; }" : "=r"(a) : "l"(p));
    return a;
}
#define CPA16(d, s) asm volatile("cp.async.cg.shared.global [%0], [%1], 16;" :: "r"(d), "l"(s))
#define CP_COMMIT() asm volatile("cp.async.commit_group;" ::: "memory")
#define CP_WAIT1()  asm volatile("cp.async.wait_group 1;" ::: "memory")
#define CP_WAIT0()  asm volatile("cp.async.wait_group 0;" ::: "memory")

__device__ __forceinline__ void ldm4(uint32_t addr, uint32_t* r){
    asm volatile("ldmatrix.sync.aligned.m8n8.x4.shared.b16 {%0,%1,%2,%3}, [%4];"
        : "=r"(r[0]), "=r"(r[1]), "=r"(r[2]), "=r"(r[3]) : "r"(addr));
}
__device__ __forceinline__ void mma16816(float* c, const uint32_t* a, const uint32_t* b){
    asm volatile("mma.sync.aligned.m16n8k16.row.col.f32.f16.f16.f32 "
        "{%0,%1,%2,%3}, {%4,%5,%6,%7}, {%8,%9}, {%0,%1,%2,%3};"
        : "+f"(c[0]), "+f"(c[1]), "+f"(c[2]), "+f"(c[3])
        : "r"(a[0]), "r"(a[1]), "r"(a[2]), "r"(a[3]), "r"(b[0]), "r"(b[1]));
}

// ---------------- scratch ----------------
__device__ __align__(256) __half g_pat[MALL*PATCHES];
__device__ __align__(256) __half g_cw[NDIM*PATCHES];
__device__ __align__(256) __half g_wqkvT[NDEPTH*QKVW*NDIM];
__device__ __align__(256) __half g_woT[NDEPTH*NDIM*NDIM];
__device__ __align__(256) __half g_w1T[NDEPTH*DMLP*NDIM];
__device__ __align__(256) __half g_w2T[NDEPTH*NDIM*DMLP];
__device__ __align__(256) float  g_x[MALL*NDIM];
__device__ __align__(256) __half g_h[MALL*NDIM];
__device__ __align__(256) __half g_qkv[MALL*QKVW];
__device__ __align__(256) float  g_scores[NBH*NTOK*NTOK];
__device__ __align__(256) __half g_p[NBH*NTOK*NTOK];
__device__ __align__(256) __half g_vt[NBH*DHEAD*NTOK];
__device__ __align__(256) __half g_o[MALL*NDIM];
__device__ __align__(256) __half g_m[MALL*DMLP];

// ---------------- prep kernels ----------------
__global__ void im2col_half(const float* __restrict__ vol, __half* __restrict__ o){
    int idx = blockIdx.x * 256 + threadIdx.x;
    int m = idx & 511, tkn = idx >> 9, n = tkn & 511, b = tkn >> 9;
    int k = m & 7, j = (m >> 3) & 7, i = m >> 6;
    int pw = n & 7, ph = (n >> 3) & 7, pd = n >> 6;
    o[idx] = __float2half_rn(vol[((long)b << 18) + (pd*8+i)*4096 + (ph*8+j)*64 + (pw*8+k)]);
}
__global__ void conv_half(const float* __restrict__ in, __half* __restrict__ o, int n){
    int idx = blockIdx.x * 256 + threadIdx.x;
    if (idx >= n) return;
    o[idx] = __float2half_rn(in[idx]);
}
__global__ void wt_half(const float* __restrict__ in, __half* __restrict__ o, int R, int C){
    __shared__ float tf[32][33];
    int z = blockIdx.z;
    const float* ip = in + (long)z * R * C;
    int r0 = blockIdx.y * 32, c0 = blockIdx.x * 32;
    int tx = threadIdx.x, ty = threadIdx.y;
#pragma unroll
    for (int i = 0; i < 4; i++)
        tf[ty + 8*i][tx] = ip[(long)(r0 + ty + 8*i) * C + c0 + tx];
    __syncthreads();
    long ob = (long)z * R * C;
#pragma unroll
    for (int i = 0; i < 4; i++)
        o[ob + (long)(c0 + ty + 8*i) * R + r0 + tx] = __float2half_rn(tf[tx][ty + 8*i]);
}

// ---------------- LN: single-pass, fp16 or fp32 out ----------------
template <int HALF>
__global__ void ln_kernel(const float* __restrict__ x, const float* __restrict__ w,
                          const float* __restrict__ bb, float* __restrict__ of,
                          __half* __restrict__ oh){
    __shared__ float red1[8], red2[8];
    const int row = blockIdx.x, t = threadIdx.x;
    const float* xp = x + (long)row * NDIM;
    float v0 = xp[t], v1 = xp[t+256], v2 = xp[t+512];
    float s1 = v0 + v1 + v2;
    float s2 = v0*v0 + v1*v1 + v2*v2;
#pragma unroll
    for (int o = 16; o; o >>= 1) {
        s1 += __shfl_xor_sync(~0u, s1, o);
        s2 += __shfl_xor_sync(~0u, s2, o);
    }
    if ((t & 31) == 0) { red1[t >> 5] = s1; red2[t >> 5] = s2; }
    __syncthreads();
    if (t < 32) {
        float r1 = (t < 8) ? red1[t] : 0.0f;
        float r2 = (t < 8) ? red2[t] : 0.0f;
#pragma unroll
        for (int o = 4; o; o >>= 1) {
            r1 += __shfl_xor_sync(~0u, r1, o);
            r2 += __shfl_xor_sync(~0u, r2, o);
        }
        if (t == 0) { red1[0] = r1; red2[0] = r2; }
    }
    __syncthreads();
    float mean = red1[0] * (1.0f / NDIM);
    float var  = red2[0] * (1.0f / NDIM) - mean * mean;
    float rs = rsqrtf(var + 1e-5f);
    float y0 = (v0-mean)*rs*w[t]     + bb[t];
    float y1 = (v1-mean)*rs*w[t+256] + bb[t+256];
    float y2 = (v2-mean)*rs*w[t+512] + bb[t+512];
    long o0 = (long)row * NDIM;
    if (HALF) {
        oh[o0+t]     = __float2half_rn(y0);
        oh[o0+t+256] = __float2half_rn(y1);
        oh[o0+t+512] = __float2half_rn(y2);
    } else {
        of[o0+t]=y0; of[o0+t+256]=y1; of[o0+t+512]=y2;
    }
}

// ---------------- softmax (fp32 scores -> fp16 P) ----------------
__global__ void softmax_half(const float* __restrict__ sc, __half* __restrict__ ph){
    __shared__ float redm[4], reds[4];
    long rb = (long)blockIdx.x * NTOK;
    const int t = threadIdx.x;
    float4 v = *reinterpret_cast<const float4*>(&sc[rb + t*4]);
    float m = fmaxf(fmaxf(v.x, v.y), fmaxf(v.z, v.w));
#pragma unroll
    for (int o = 16; o; o >>= 1) m = fmaxf(m, __shfl_xor_sync(~0u, m, o));
    if ((t & 31) == 0) redm[t >> 5] = m;
    __syncthreads();
    m = fmaxf(fmaxf(redm[0], redm[1]), fmaxf(redm[2], redm[3]));
    v.x = __expf(v.x-m); v.y = __expf(v.y-m); v.z = __expf(v.z-m); v.w = __expf(v.w-m);
    float s = v.x + v.y + v.z + v.w;
#pragma unroll
    for (int o = 16; o; o >>= 1) s += __shfl_xor_sync(~0u, s, o);
    if ((t & 31) == 0) reds[t >> 5] = s;
    __syncthreads();
    s = reds[0] + reds[1] + reds[2] + reds[3];
    float inv = 1.0f / s;
    long off = rb + t*4;
    reinterpret_cast<__half2*>(ph+off)[0] =
        __halves2half2(__float2half_rn(v.x*inv), __float2half_rn(v.y*inv));
    reinterpret_cast<__half2*>(ph+off)[1] =
        __halves2half2(__float2half_rn(v.z*inv), __float2half_rn(v.w*inv));
}

// ---------------- pure-fp16 GEMM via mma.sync ----------------
// C[M,N] = A[M,K] @ B[N,K]^T. 1 MMA per product. 3-stage cp.async ring.
// EPI: 0 fp32*scale | 1 fp32 residual+=acc+bias | 2 tanh(acc+bias)->fp16
//      3 acc+bias+pos->fp32 | 4 acc->fp16 | 5 qkv fused (Q,K rows; V->vt transposed)
template <int BM, int BN>
__device__ __forceinline__ void ld_stage(uint32_t sb, int tid,
    const __half* pA, const __half* pB,
    long long lda, long long ldb, int row0, int col0, int k0){
    constexpr int ASZ = BM*80;
#pragma unroll
    for (int i = 0; i < BM/64; i++) {
        int ch = tid + i*256;
        int r = ch >> 2, c = ch & 3;
        uint32_t so = r*80 + c*16;
        CPA16(sb + so, pA + (long long)(row0 + r) * lda + k0 + c*8);
    }
#pragma unroll
    for (int i = 0; i < BN/64; i++) {
        int ch = tid + i*256;
        int r = ch >> 2, c = ch & 3;
        uint32_t so = r*80 + c*16;
        CPA16(sb + ASZ + so, pB + (long long)(col0 + r) * ldb + k0 + c*8);
    }
}

template <int BM, int BN, int EPI, int OCC>
__global__ void __launch_bounds__(256, OCC) mma_gemm(
    const __half* __restrict__ A, long long lda, long long aSB, long long aSH,
    const __half* __restrict__ B, long long ldb, long long bSB, long long bSH,
    float* __restrict__ Cf, __half* __restrict__ Oh, __half* __restrict__ Vt,
    long long ldc, long long cSB, long long cSH,
    const float* __restrict__ bias, const float* __restrict__ pos,
    float scale, int K, int heads)
{
    extern __shared__ __align__(128) char smem_raw[];
    uint32_t sb = smem_u32(smem_raw);
    constexpr int ASZ = BM*80;
    constexpr int BUF = (BM+BN)*80;
    constexpr int MW = BM/32;
    constexpr int NW = 8/MW;
    constexpr int WN = BN/NW;
    constexpr int NP = WN/16;
    constexpr int NT = WN/8;

    const int tid = threadIdx.x, lane = tid & 31, warp = tid >> 5;
    const int warpM = warp % MW, warpN = warp / MW;
    const int z = blockIdx.z, zb = z / heads, zh = z % heads;
    const __half* pA = A + zb*aSB + zh*aSH;
    const __half* pB = B + zb*bSB + zh*bSH;
    const long long cOff = zb*cSB + zh*cSH;
    const int row0 = blockIdx.y * BM, col0 = blockIdx.x * BN;

    float acc[2][NT][4];
#pragma unroll
    for (int a = 0; a < 2; a++)
#pragma unroll
        for (int b = 0; b < NT; b++)
#pragma unroll
            for (int c = 0; c < 4; c++) acc[a][b][c] = 0.0f;

    const int nst = K >> 5;
    ld_stage<BM,BN>(sb, tid, pA, pB, lda, ldb, row0, col0, 0);
    CP_COMMIT();
    if (nst > 1) {
        ld_stage<BM,BN>(sb + BUF, tid, pA, pB, lda, ldb, row0, col0, 32);
        CP_COMMIT();
    }

    const int L = lane & 7, jj = lane >> 3;
    for (int st = 0; st < nst; st++) {
        if (st < nst - 1) CP_WAIT1(); else CP_WAIT0();
        __syncthreads();
        if (st + 2 < nst) {
            ld_stage<BM,BN>(sb + ((st+2)%3)*BUF, tid, pA, pB,
                            lda, ldb, row0, col0, (st+2)*32);
            CP_COMMIT();
        }
        uint32_t base = sb + (st % 3) * BUF;
#pragma unroll
        for (int ks = 0; ks < 2; ks++) {
            uint32_t a_[2][4];
#pragma unroll
            for (int mi = 0; mi < 2; mi++) {
                int mrow = warpM*32 + mi*16 + (jj & 1)*8 + L;
                int kcol = ks*16 + (jj >> 1)*8;
                ldm4(base + mrow*80 + kcol*2, a_[mi]);
            }
            uint32_t b_[NP][4];
#pragma unroll
            for (int np = 0; np < NP; np++) {
                int nrow = warpN*WN + np*16 + (jj >> 1)*8 + L;
                int kcol = ks*16 + (jj & 1)*8;
                ldm4(base + ASZ + nrow*80 + kcol*2, b_[np]);
            }
#pragma unroll
            for (int mi = 0; mi < 2; mi++)
#pragma unroll
                for (int np = 0; np < NP; np++)
#pragma unroll
                    for (int si = 0; si < 2; si++) {
                        uint32_t f[2] = { b_[np][si*2], b_[np][si*2+1] };
                        mma16816(acc[mi][np*2 + si], a_[mi], f);
                    }
        }
    }

#pragma unroll
    for (int mi = 0; mi < 2; mi++)
#pragma unroll
        for (int nt = 0; nt < NT; nt++) {
            float* c = acc[mi][nt];
            int col = col0 + warpN*WN + nt*8 + (lane & 3)*2;
#pragma unroll
            for (int hf = 0; hf < 2; hf++) {
                int row = row0 + warpM*32 + mi*16 + (lane >> 2) + hf*8;
                float v0 = c[hf*2 + 0], v1 = c[hf*2 + 1];
                if (EPI == 0) {
                    float2* cp = reinterpret_cast<float2*>(Cf + cOff + (long long)row*ldc + col);
                    *cp = make_float2(v0*scale, v1*scale);
                } else if (EPI == 1) {
                    float2* cp = reinterpret_cast<float2*>(Cf + cOff + (long long)row*ldc + col);
                    float2 old = *cp;
                    *cp = make_float2(old.x + v0 + bias[col], old.y + v1 + bias[col+1]);
                } else if (EPI == 3) {
                    const float2* pp = reinterpret_cast<const float2*>(
                        pos + (long long)(row & (NTOK-1))*ldc + col);
                    float2 pv = *pp;
                    float2* cp = reinterpret_cast<float2*>(Cf + (long long)row*ldc + col);
                    *cp = make_float2(v0 + bias[col] + pv.x, v1 + bias[col+1] + pv.y);
                } else if (EPI == 5) {
                    if (col0 < 2*NDIM) {
                        long long off = (long long)row*ldc + col;
                        *reinterpret_cast<__half2*>(Oh + off) =
                            __halves2half2(__float2half_rn(v0), __float2half_rn(v1));
                    } else {
                        int bb2 = row >> 9, t2 = row & (NTOK-1);
                        int hd = col - 2*NDIM, hh2 = hd >> 6, d = hd & (DHEAD-1);
                        long vtb = ((long)(bb2*NHEADS + hh2)*DHEAD + d)*NTOK + t2;
                        Vt[vtb] = __float2half_rn(v0);
                        Vt[vtb + NTOK] = __float2half_rn(v1);
                    }
                } else {
                    if (EPI == 2) {
                        v0 = tanhf(v0 + bias[col]);
                        v1 = tanhf(v1 + bias[col+1]);
                    }
                    long long off = cOff + (long long)row*ldc + col;
                    *reinterpret_cast<__half2*>(Oh + off) =
                        __halves2half2(__float2half_rn(v0), __float2half_rn(v1));
                }
            }
        }
}

// ---------------- host ----------------
extern "C" void kernel_launch(void* const* d_in, const int* in_sizes, int n_in,
                              void* d_out, int out_size)
{
    const float* volume    = (const float*)d_in[0];
    const float* conv_w    = (const float*)d_in[1];
    const float* conv_b    = (const float*)d_in[2];
    const float* pos_embed = (const float*)d_in[3];
    const float* ln1_w     = (const float*)d_in[4];
    const float* ln1_b     = (const float*)d_in[5];
    const float* w_qkv     = (const float*)d_in[6];
    const float* w_o       = (const float*)d_in[7];
    const float* b_o       = (const float*)d_in[8];
    const float* ln2_w     = (const float*)d_in[9];
    const float* ln2_b     = (const float*)d_in[10];
    const float* w1        = (const float*)d_in[11];
    const float* b1        = (const float*)d_in[12];
    const float* w2        = (const float*)d_in[13];
    const float* b2        = (const float*)d_in[14];
    const float* lnf_w     = (const float*)d_in[15];
    const float* lnf_b     = (const float*)d_in[16];
    float* out = (float*)d_out;

    __half *pat,*cw,*wqT,*woT,*w1T,*w2T,*h,*qkv,*p,*vt,*o,*m;
    float *x, *scores;
    cudaGetSymbolAddress((void**)&pat, g_pat);
    cudaGetSymbolAddress((void**)&cw, g_cw);
    cudaGetSymbolAddress((void**)&wqT, g_wqkvT);
    cudaGetSymbolAddress((void**)&woT, g_woT);
    cudaGetSymbolAddress((void**)&w1T, g_w1T);
    cudaGetSymbolAddress((void**)&w2T, g_w2T);
    cudaGetSymbolAddress((void**)&x, g_x);
    cudaGetSymbolAddress((void**)&h, g_h);
    cudaGetSymbolAddress((void**)&qkv, g_qkv);
    cudaGetSymbolAddress((void**)&scores, g_scores);
    cudaGetSymbolAddress((void**)&p, g_p);
    cudaGetSymbolAddress((void**)&vt, g_vt);
    cudaGetSymbolAddress((void**)&o, g_o);
    cudaGetSymbolAddress((void**)&m, g_m);

    const int S_128_128 = 3*(128+128)*80;   // 61440
    const int S_128_192 = 3*(128+192)*80;   // 76800
    const int S_64_64   = 3*(64+64)*80;     // 30720
    cudaFuncSetAttribute((const void*)mma_gemm<128,128,5,2>, cudaFuncAttributeMaxDynamicSharedMemorySize, S_128_128);
    cudaFuncSetAttribute((const void*)mma_gemm<128,128,0,2>, cudaFuncAttributeMaxDynamicSharedMemorySize, S_128_128);
    cudaFuncSetAttribute((const void*)mma_gemm<64,64,4,2>,   cudaFuncAttributeMaxDynamicSharedMemorySize, S_64_64);
    cudaFuncSetAttribute((const void*)mma_gemm<64,64,1,2>,   cudaFuncAttributeMaxDynamicSharedMemorySize, S_64_64);
    cudaFuncSetAttribute((const void*)mma_gemm<64,64,3,2>,   cudaFuncAttributeMaxDynamicSharedMemorySize, S_64_64);
    cudaFuncSetAttribute((const void*)mma_gemm<128,192,2,2>, cudaFuncAttributeMaxDynamicSharedMemorySize, S_128_192);

    dim3 tb(32, 8);

    im2col_half<<<(MALL*PATCHES)/256, 256>>>(volume, pat);
    conv_half<<<(NDIM*PATCHES)/256, 256>>>(conv_w, cw, NDIM*PATCHES);
    wt_half<<<dim3(QKVW/32, NDIM/32, NDEPTH), tb>>>(w_qkv, wqT, NDIM, QKVW);
    wt_half<<<dim3(NDIM/32, NDIM/32, NDEPTH), tb>>>(w_o, woT, NDIM, NDIM);
    wt_half<<<dim3(DMLP/32, NDIM/32, NDEPTH), tb>>>(w1, w1T, NDIM, DMLP);
    wt_half<<<dim3(NDIM/32, DMLP/32, NDEPTH), tb>>>(w2, w2T, DMLP, NDIM);

    // patch embed: x = patches @ conv_w^T + conv_b + pos
    mma_gemm<64,64,3,2><<<dim3(NDIM/64, MALL/64, 1), 256, S_64_64>>>(
        pat, PATCHES, 0, 0, cw, PATCHES, 0, 0,
        x, nullptr, nullptr, NDIM, 0, 0, conv_b, pos_embed, 1.f, PATCHES, 1);

    for (int l = 0; l < NDEPTH; ++l) {
        ln_kernel<1><<<MALL, 256>>>(x, ln1_w + l*NDIM, ln1_b + l*NDIM, nullptr, h);
        // QKV fused: Q,K rows stored; V transposed into vt
        mma_gemm<128,128,5,2><<<dim3(QKVW/128, MALL/128, 1), 256, S_128_128>>>(
            h, NDIM, 0, 0, wqT + (long)l*QKVW*NDIM, NDIM, 0, 0,
            nullptr, qkv, vt, QKVW, 0, 0, nullptr, nullptr, 1.f, NDIM, 1);
        // QK
        mma_gemm<128,128,0,2><<<dim3(NTOK/128, NTOK/128, NBH), 256, S_128_128>>>(
            qkv, QKVW, (long long)NTOK*QKVW, DHEAD,
            qkv + NDIM, QKVW, (long long)NTOK*QKVW, DHEAD,
            scores, nullptr, nullptr, NTOK, (long long)NHEADS*NTOK*NTOK, (long long)NTOK*NTOK,
            nullptr, nullptr, 0.125f, DHEAD, NHEADS);
        softmax_half<<<NBH*NTOK, 128>>>(scores, p);
        // PV
        mma_gemm<64,64,4,2><<<dim3(1, NTOK/64, NBH), 256, S_64_64>>>(
            p, NTOK, (long long)NHEADS*NTOK*NTOK, (long long)NTOK*NTOK,
            vt, NTOK, (long long)NHEADS*DHEAD*NTOK, (long long)DHEAD*NTOK,
            nullptr, o, nullptr, NDIM, (long long)NTOK*NDIM, DHEAD,
            nullptr, nullptr, 1.f, NTOK, NHEADS);
        mma_gemm<64,64,1,2><<<dim3(NDIM/64, MALL/64, 1), 256, S_64_64>>>(
            o, NDIM, 0, 0, woT + (long)l*NDIM*NDIM, NDIM, 0, 0,
            x, nullptr, nullptr, NDIM, 0, 0, b_o + l*NDIM, nullptr, 1.f, NDIM, 1);
        ln_kernel<1><<<MALL, 256>>>(x, ln2_w + l*NDIM, ln2_b + l*NDIM, nullptr, h);
        mma_gemm<128,192,2,2><<<dim3(DMLP/192, MALL/128, 1), 256, S_128_192>>>(
            h, NDIM, 0, 0, w1T + (long)l*DMLP*NDIM, NDIM, 0, 0,
            nullptr, m, nullptr, DMLP, 0, 0, b1 + l*DMLP, nullptr, 1.f, NDIM, 1);
        mma_gemm<64,64,1,2><<<dim3(NDIM/64, MALL/64, 1), 256, S_64_64>>>(
            m, DMLP, 0, 0, w2T + (long)l*NDIM*DMLP, DMLP, 0, 0,
            x, nullptr, nullptr, NDIM, 0, 0, b2 + l*NDIM, nullptr, 1.f, DMLP, 1);
    }

    ln_kernel<0><<<MALL, 256>>>(x, lnf_w, lnf_b, out, nullptr);
}